// round 1
// baseline (speedup 1.0000x reference)
#include <cuda_runtime.h>
#include <math.h>

#define BB 2
#define SS 2048
#define DD 1024
#define HH 16
#define HD 64
#define FF 4096
#define NN (BB*SS)   // 4096 tokens

// ---------------- scratch (static device globals; no allocs) ----------------
__device__ float g_xnorm [NN*DD];
__device__ float g_q     [NN*DD];   // [B,H,S,hd]
__device__ float g_k     [NN*DD];   // [B,H,S,hd]
__device__ float g_v     [NN*DD];   // [B,H,S,hd]
__device__ float g_attn  [NN*DD];   // [B,S,D] merged heads
__device__ float g_x1    [NN*DD];   // x + attn_out
__device__ float g_xnorm2[NN*DD];
__device__ float g_h     [NN*FF];   // FFN hidden

// ---------------- LayerNorm: one block per row, 256 thr, float4 ----------------
__global__ __launch_bounds__(256) void ln_kernel(const float* __restrict__ x,
                                                 const float* __restrict__ gamma,
                                                 const float* __restrict__ beta,
                                                 float* __restrict__ out)
{
    int row = blockIdx.x;
    const float4* xr = reinterpret_cast<const float4*>(x + (size_t)row * DD);
    float4 v = xr[threadIdx.x];

    float s  = v.x + v.y + v.z + v.w;
    float sq = v.x*v.x + v.y*v.y + v.z*v.z + v.w*v.w;

    // warp reduce
    #pragma unroll
    for (int o = 16; o > 0; o >>= 1) {
        s  += __shfl_xor_sync(0xffffffffu, s,  o);
        sq += __shfl_xor_sync(0xffffffffu, sq, o);
    }
    __shared__ float ps[8], psq[8];
    int wid = threadIdx.x >> 5, lane = threadIdx.x & 31;
    if (lane == 0) { ps[wid] = s; psq[wid] = sq; }
    __syncthreads();
    float ts = 0.f, tsq = 0.f;
    #pragma unroll
    for (int i = 0; i < 8; i++) { ts += ps[i]; tsq += psq[i]; }

    float mu   = ts * (1.0f / DD);
    float var  = tsq * (1.0f / DD) - mu * mu;
    float rstd = rsqrtf(var + 1e-5f);

    float4 g = reinterpret_cast<const float4*>(gamma)[threadIdx.x];
    float4 b = reinterpret_cast<const float4*>(beta )[threadIdx.x];
    float4 o4;
    o4.x = (v.x - mu) * rstd * g.x + b.x;
    o4.y = (v.y - mu) * rstd * g.y + b.y;
    o4.z = (v.z - mu) * rstd * g.z + b.z;
    o4.w = (v.w - mu) * rstd * g.w + b.w;
    reinterpret_cast<float4*>(out + (size_t)row * DD)[threadIdx.x] = o4;
}

// ---------------- Generic tiled GEMM: C = A[MxK] @ W[KxNc] + bias, epilogue modes ----------------
#define MODE_PLAIN 0
#define MODE_QKV   1   // scatter to [B,H,S,hd]
#define MODE_RESID 2   // += resid[r*Nc+c]
#define MODE_RELU  3

__global__ __launch_bounds__(256) void gemm_kernel(const float* __restrict__ A,
                                                   const float* __restrict__ W,
                                                   const float* __restrict__ bias,
                                                   const float* __restrict__ resid,
                                                   float* __restrict__ C,
                                                   int M, int K, int Nc, int mode)
{
    __shared__ float As[8][128];
    __shared__ float Ws[8][128];

    int tid = threadIdx.x;
    int tx = tid & 15, ty = tid >> 4;
    int rowBase = blockIdx.y * 128;
    int colBase = blockIdx.x * 128;

    float acc[8][8];
    #pragma unroll
    for (int i = 0; i < 8; i++)
        #pragma unroll
        for (int j = 0; j < 8; j++) acc[i][j] = 0.f;

    int aRow = tid >> 1;            // 0..127
    int aCol = (tid & 1) * 4;       // 0 or 4
    int wRow = tid >> 5;            // 0..7
    int wCol = (tid & 31) * 4;      // 0..124

    const float* Aptr = A + (size_t)(rowBase + aRow) * K + aCol;
    const float* Wptr = W + (size_t)wRow * Nc + colBase + wCol;

    for (int k0 = 0; k0 < K; k0 += 8) {
        float4 av = *reinterpret_cast<const float4*>(Aptr + k0);
        float4 wv = *reinterpret_cast<const float4*>(Wptr + (size_t)k0 * Nc);
        As[aCol+0][aRow] = av.x;
        As[aCol+1][aRow] = av.y;
        As[aCol+2][aRow] = av.z;
        As[aCol+3][aRow] = av.w;
        *reinterpret_cast<float4*>(&Ws[wRow][wCol]) = wv;
        __syncthreads();

        #pragma unroll
        for (int kk = 0; kk < 8; kk++) {
            float ra[8], rb[8];
            #pragma unroll
            for (int i = 0; i < 8; i++) ra[i] = As[kk][ty*8 + i];
            #pragma unroll
            for (int j = 0; j < 8; j++) rb[j] = Ws[kk][tx*8 + j];
            #pragma unroll
            for (int i = 0; i < 8; i++)
                #pragma unroll
                for (int j = 0; j < 8; j++)
                    acc[i][j] += ra[i] * rb[j];
        }
        __syncthreads();
    }

    #pragma unroll
    for (int i = 0; i < 8; i++) {
        int r = rowBase + ty*8 + i;
        #pragma unroll
        for (int j = 0; j < 8; j++) {
            int c = colBase + tx*8 + j;
            float v = acc[i][j] + bias[c];
            if (mode == MODE_RELU) v = fmaxf(v, 0.f);
            size_t oidx;
            if (mode == MODE_QKV) {
                int b = r >> 11, s = r & 2047;
                int h = c >> 6,  jj = c & 63;
                oidx = ((size_t)((b*HH + h)*SS + s)) * HD + jj;
            } else {
                oidx = (size_t)r * Nc + c;
                if (mode == MODE_RESID) v += resid[oidx];
            }
            C[oidx] = v;
        }
    }
}

// ---------------- RoPE (in place on [B,H,S,hd]); scale applied after rotation ----------------
__global__ __launch_bounds__(256) void rope_kernel(float* __restrict__ t, float scale)
{
    int idx = blockIdx.x * blockDim.x + threadIdx.x;   // pair index over BH*S*32
    int p = idx & 31;
    int s = (idx >> 5) & (SS - 1);
    float2 v = reinterpret_cast<float2*>(t)[idx];
    float inv = powf(10000.0f, -(float)p / 32.0f);
    float a = (float)s * inv;
    float sn, cs;
    sincosf(a, &sn, &cs);
    float x0 = v.x * cs - v.y * sn;
    float x1 = v.x * sn + v.y * cs;
    reinterpret_cast<float2*>(t)[idx] = make_float2(x0 * scale, x1 * scale);
}

// ---------------- Flash attention fp32: 64 queries x 64 keys tiles, hd=64 ----------------
// grid (S/64, B*H), 256 threads; 4x4 microtile per thread (16x16 thread grid)
#define ATTN_SMEM (4 * 64 * 68 * 4)

__global__ __launch_bounds__(256) void attn_kernel(const float* __restrict__ Q,
                                                   const float* __restrict__ Kg,
                                                   const float* __restrict__ V,
                                                   float* __restrict__ Out)
{
    extern __shared__ float sm[];
    float (*QsT)[68] = reinterpret_cast<float(*)[68]>(sm);             // [d][row]
    float (*KsT)[68] = reinterpret_cast<float(*)[68]>(sm + 64*68);     // [d][key]
    float (*Vs) [68] = reinterpret_cast<float(*)[68]>(sm + 2*64*68);   // [key][d]
    float (*Ps) [68] = reinterpret_cast<float(*)[68]>(sm + 3*64*68);   // [row][key]

    const int bh = blockIdx.y;           // 0..31
    const int q0 = blockIdx.x * 64;
    const int tid = threadIdx.x;
    const int tx = tid & 15, ty = tid >> 4;

    const float* Qb = Q  + ((size_t)bh * SS + q0) * HD;
    const float* Kb = Kg + (size_t)bh * SS * HD;
    const float* Vb = V  + (size_t)bh * SS * HD;

    // load Q tile transposed (once)
    {
        int r  = tid >> 2;          // 0..63
        int c0 = (tid & 3) * 16;    // 0,16,32,48
        #pragma unroll
        for (int u = 0; u < 4; u++) {
            float4 v4 = *reinterpret_cast<const float4*>(Qb + (size_t)r*HD + c0 + u*4);
            QsT[c0+u*4+0][r] = v4.x;
            QsT[c0+u*4+1][r] = v4.y;
            QsT[c0+u*4+2][r] = v4.z;
            QsT[c0+u*4+3][r] = v4.w;
        }
    }

    float m[4], l[4], acc[4][4];
    #pragma unroll
    for (int i = 0; i < 4; i++) {
        m[i] = -1e30f; l[i] = 0.f;
        #pragma unroll
        for (int j = 0; j < 4; j++) acc[i][j] = 0.f;
    }

    for (int kb = 0; kb < SS; kb += 64) {
        __syncthreads();   // prior tile fully consumed; Q visible on first iter
        {
            int r  = tid >> 2;
            int c0 = (tid & 3) * 16;
            #pragma unroll
            for (int u = 0; u < 4; u++) {
                float4 kv = *reinterpret_cast<const float4*>(Kb + (size_t)(kb + r)*HD + c0 + u*4);
                KsT[c0+u*4+0][r] = kv.x;
                KsT[c0+u*4+1][r] = kv.y;
                KsT[c0+u*4+2][r] = kv.z;
                KsT[c0+u*4+3][r] = kv.w;
                float4 vv = *reinterpret_cast<const float4*>(Vb + (size_t)(kb + r)*HD + c0 + u*4);
                *reinterpret_cast<float4*>(&Vs[r][c0+u*4]) = vv;
            }
        }
        __syncthreads();

        // S = Q K^T (4x4 per thread)
        float s4[4][4];
        #pragma unroll
        for (int i = 0; i < 4; i++)
            #pragma unroll
            for (int j = 0; j < 4; j++) s4[i][j] = 0.f;

        #pragma unroll 8
        for (int kk = 0; kk < 64; kk++) {
            float4 qa = *reinterpret_cast<const float4*>(&QsT[kk][ty*4]);
            float4 ka = *reinterpret_cast<const float4*>(&KsT[kk][tx*4]);
            float ra[4] = {qa.x, qa.y, qa.z, qa.w};
            float rb[4] = {ka.x, ka.y, ka.z, ka.w};
            #pragma unroll
            for (int i = 0; i < 4; i++)
                #pragma unroll
                for (int j = 0; j < 4; j++)
                    s4[i][j] += ra[i] * rb[j];
        }

        // online softmax (row stats reduced over the 16-lane tx group)
        #pragma unroll
        for (int i = 0; i < 4; i++) {
            float mx = fmaxf(fmaxf(s4[i][0], s4[i][1]), fmaxf(s4[i][2], s4[i][3]));
            #pragma unroll
            for (int o = 1; o < 16; o <<= 1)
                mx = fmaxf(mx, __shfl_xor_sync(0xffffffffu, mx, o));
            float mnew  = fmaxf(m[i], mx);
            float alpha = __expf(m[i] - mnew);
            float rs = 0.f;
            #pragma unroll
            for (int j = 0; j < 4; j++) {
                s4[i][j] = __expf(s4[i][j] - mnew);
                rs += s4[i][j];
            }
            #pragma unroll
            for (int o = 1; o < 16; o <<= 1)
                rs += __shfl_xor_sync(0xffffffffu, rs, o);
            l[i] = l[i] * alpha + rs;
            m[i] = mnew;
            #pragma unroll
            for (int j = 0; j < 4; j++) acc[i][j] *= alpha;
        }

        // stage P to smem
        #pragma unroll
        for (int i = 0; i < 4; i++)
            *reinterpret_cast<float4*>(&Ps[ty*4+i][tx*4]) =
                make_float4(s4[i][0], s4[i][1], s4[i][2], s4[i][3]);
        __syncthreads();

        // O += P @ V
        #pragma unroll 4
        for (int kk = 0; kk < 64; kk += 4) {
            float pr[4][4];
            #pragma unroll
            for (int i = 0; i < 4; i++) {
                float4 t4 = *reinterpret_cast<const float4*>(&Ps[ty*4+i][kk]);
                pr[i][0] = t4.x; pr[i][1] = t4.y; pr[i][2] = t4.z; pr[i][3] = t4.w;
            }
            #pragma unroll
            for (int u = 0; u < 4; u++) {
                float4 vv = *reinterpret_cast<const float4*>(&Vs[kk+u][tx*4]);
                #pragma unroll
                for (int i = 0; i < 4; i++) {
                    acc[i][0] += pr[i][u] * vv.x;
                    acc[i][1] += pr[i][u] * vv.y;
                    acc[i][2] += pr[i][u] * vv.z;
                    acc[i][3] += pr[i][u] * vv.w;
                }
            }
        }
    }

    // write O / l, merged-head layout [B,S,D]
    int b = bh >> 4, h = bh & 15;
    #pragma unroll
    for (int i = 0; i < 4; i++) {
        int srow = q0 + ty*4 + i;
        float inv = 1.f / l[i];
        float4 o = make_float4(acc[i][0]*inv, acc[i][1]*inv, acc[i][2]*inv, acc[i][3]*inv);
        *reinterpret_cast<float4*>(&Out[((size_t)(b*SS + srow))*DD + h*HD + tx*4]) = o;
    }
}

// ---------------- host launch ----------------
extern "C" void kernel_launch(void* const* d_in, const int* in_sizes, int n_in,
                              void* d_out, int out_size)
{
    const float* x     = (const float*)d_in[0];
    const float* Wq    = (const float*)d_in[1];
    const float* bq    = (const float*)d_in[2];
    const float* Wk    = (const float*)d_in[3];
    const float* bk    = (const float*)d_in[4];
    const float* Wv    = (const float*)d_in[5];
    const float* bv    = (const float*)d_in[6];
    const float* Wo    = (const float*)d_in[7];
    const float* bo    = (const float*)d_in[8];
    const float* W1    = (const float*)d_in[9];
    const float* b1    = (const float*)d_in[10];
    const float* W2    = (const float*)d_in[11];
    const float* b2    = (const float*)d_in[12];
    const float* g1    = (const float*)d_in[13];
    const float* beta1 = (const float*)d_in[14];
    const float* g2    = (const float*)d_in[15];
    const float* beta2 = (const float*)d_in[16];
    float* out = (float*)d_out;

    float *xnorm, *q, *k, *v, *attn, *x1, *xnorm2, *hbuf;
    cudaGetSymbolAddress((void**)&xnorm,  g_xnorm);
    cudaGetSymbolAddress((void**)&q,      g_q);
    cudaGetSymbolAddress((void**)&k,      g_k);
    cudaGetSymbolAddress((void**)&v,      g_v);
    cudaGetSymbolAddress((void**)&attn,   g_attn);
    cudaGetSymbolAddress((void**)&x1,     g_x1);
    cudaGetSymbolAddress((void**)&xnorm2, g_xnorm2);
    cudaGetSymbolAddress((void**)&hbuf,   g_h);

    // LN1
    ln_kernel<<<NN, 256>>>(x, g1, beta1, xnorm);

    // QKV projections (epilogue scatters to [B,H,S,hd])
    dim3 gdd(DD/128, NN/128);
    gemm_kernel<<<gdd, 256>>>(xnorm, Wq, bq, nullptr, q, NN, DD, DD, MODE_QKV);
    gemm_kernel<<<gdd, 256>>>(xnorm, Wk, bk, nullptr, k, NN, DD, DD, MODE_QKV);
    gemm_kernel<<<gdd, 256>>>(xnorm, Wv, bv, nullptr, v, NN, DD, DD, MODE_QKV);

    // RoPE (q also gets the 1/sqrt(hd) scale)
    int ropeBlocks = (BB*HH*SS*(HD/2)) / 256;
    rope_kernel<<<ropeBlocks, 256>>>(q, 0.125f);
    rope_kernel<<<ropeBlocks, 256>>>(k, 1.0f);

    // flash attention
    cudaFuncSetAttribute(attn_kernel, cudaFuncAttributeMaxDynamicSharedMemorySize, ATTN_SMEM);
    attn_kernel<<<dim3(SS/64, BB*HH), 256, ATTN_SMEM>>>(q, k, v, attn);

    // O projection + residual: x1 = x + attn @ Wo + bo
    gemm_kernel<<<gdd, 256>>>(attn, Wo, bo, x, x1, NN, DD, DD, MODE_RESID);

    // LN2
    ln_kernel<<<NN, 256>>>(x1, g2, beta2, xnorm2);

    // FFN
    gemm_kernel<<<dim3(FF/128, NN/128), 256>>>(xnorm2, W1, b1, nullptr, hbuf, NN, DD, FF, MODE_RELU);
    gemm_kernel<<<gdd, 256>>>(hbuf, W2, b2, x1, out, NN, FF, DD, MODE_RESID);
}

// round 4
// speedup vs baseline: 1.8688x; 1.8688x over previous
#include <cuda_runtime.h>
#include <cuda_bf16.h>
#include <math.h>
#include <stdint.h>

#define BB 2
#define SS 2048
#define DD 1024
#define HH 16
#define HD 64
#define FF 4096
#define NN (BB*SS)   // 4096 tokens

// ---------------- scratch (static device globals; no allocs) ----------------
__device__ float g_qkv [3u*NN*DD];   // q,k,v each [B,H,S,hd]
__device__ float g_attn[NN*DD];      // [B,S,D]
__device__ float g_x1  [NN*DD];      // x + attn_out
__device__ __nv_bfloat16 g_xn_h [NN*DD], g_xn_l [NN*DD];
__device__ __nv_bfloat16 g_xn2_h[NN*DD], g_xn2_l[NN*DD];
__device__ __nv_bfloat16 g_at_h [NN*DD], g_at_l [NN*DD];
__device__ __nv_bfloat16 g_h_h  [(size_t)NN*FF], g_h_l[(size_t)NN*FF];
__device__ __nv_bfloat16 g_qkvt_h[3*DD*DD], g_qkvt_l[3*DD*DD]; // [3072,1024] (W^T)
__device__ __nv_bfloat16 g_wot_h [DD*DD],   g_wot_l [DD*DD];   // [1024,1024]
__device__ __nv_bfloat16 g_w1t_h [FF*DD],   g_w1t_l [FF*DD];   // [4096,1024]
__device__ __nv_bfloat16 g_w2t_h [DD*FF],   g_w2t_l [DD*FF];   // [1024,4096]
__device__ float g_bqkv[3*DD];

// ---------------- helpers ----------------
__device__ __forceinline__ uint32_t smem_u32(const void* p) {
    return (uint32_t)__cvta_generic_to_shared(p);
}
__device__ __forceinline__ void cp16(uint32_t s, const void* g) {
    asm volatile("cp.async.cg.shared.global [%0], [%1], 16;" :: "r"(s), "l"(g));
}
__device__ __forceinline__ void cp_commit() {
    asm volatile("cp.async.commit_group;" ::: "memory");
}
__device__ __forceinline__ void ldsm4(uint32_t* r, uint32_t addr) {
    asm volatile("ldmatrix.sync.aligned.m8n8.x4.shared.b16 {%0,%1,%2,%3}, [%4];"
        : "=r"(r[0]), "=r"(r[1]), "=r"(r[2]), "=r"(r[3]) : "r"(addr));
}
__device__ __forceinline__ void mma_bf16(float* d, const uint32_t* a, const uint32_t* b) {
    asm volatile("mma.sync.aligned.m16n8k16.row.col.f32.bf16.bf16.f32 "
        "{%0,%1,%2,%3}, {%4,%5,%6,%7}, {%8,%9}, {%0,%1,%2,%3};"
        : "+f"(d[0]), "+f"(d[1]), "+f"(d[2]), "+f"(d[3])
        : "r"(a[0]), "r"(a[1]), "r"(a[2]), "r"(a[3]), "r"(b[0]), "r"(b[1]));
}
__device__ __forceinline__ void split1(float x, unsigned short& h, unsigned short& l) {
    __nv_bfloat16 hb = __float2bfloat16(x);
    float hf = __bfloat162float(hb);
    __nv_bfloat16 lb = __float2bfloat16(x - hf);
    h = __bfloat16_as_ushort(hb);
    l = __bfloat16_as_ushort(lb);
}
// swizzled offset inside a 128-row x 64B tile: (row, 16B-chunk c in 0..3)
__device__ __forceinline__ uint32_t tile_off(int r, int c) {
    return (uint32_t)(((r >> 1) * 128) + (((((r & 1) << 2) | c) ^ ((r >> 1) & 7)) << 4));
}

// ---------------- LayerNorm with bf16 hi/lo split output ----------------
__global__ __launch_bounds__(256) void ln_split(const float* __restrict__ x,
                                                const float* __restrict__ gamma,
                                                const float* __restrict__ beta,
                                                __nv_bfloat16* __restrict__ oh,
                                                __nv_bfloat16* __restrict__ ol)
{
    int row = blockIdx.x;
    const float4* xr = reinterpret_cast<const float4*>(x + (size_t)row * DD);
    float4 v = xr[threadIdx.x];

    float s  = v.x + v.y + v.z + v.w;
    float sq = v.x*v.x + v.y*v.y + v.z*v.z + v.w*v.w;
    #pragma unroll
    for (int o = 16; o > 0; o >>= 1) {
        s  += __shfl_xor_sync(0xffffffffu, s,  o);
        sq += __shfl_xor_sync(0xffffffffu, sq, o);
    }
    __shared__ float ps[8], psq[8];
    int wid = threadIdx.x >> 5, lane = threadIdx.x & 31;
    if (lane == 0) { ps[wid] = s; psq[wid] = sq; }
    __syncthreads();
    float ts = 0.f, tsq = 0.f;
    #pragma unroll
    for (int i = 0; i < 8; i++) { ts += ps[i]; tsq += psq[i]; }

    float mu   = ts * (1.0f / DD);
    float var  = tsq * (1.0f / DD) - mu * mu;
    float rstd = rsqrtf(var + 1e-5f);

    float4 g = reinterpret_cast<const float4*>(gamma)[threadIdx.x];
    float4 b = reinterpret_cast<const float4*>(beta )[threadIdx.x];
    float o0 = (v.x - mu) * rstd * g.x + b.x;
    float o1 = (v.y - mu) * rstd * g.y + b.y;
    float o2 = (v.z - mu) * rstd * g.z + b.z;
    float o3 = (v.w - mu) * rstd * g.w + b.w;

    unsigned short h0,h1,h2,h3, l0,l1,l2,l3;
    split1(o0,h0,l0); split1(o1,h1,l1); split1(o2,h2,l2); split1(o3,h3,l3);
    uint2 hv = make_uint2((uint32_t)h0 | ((uint32_t)h1<<16), (uint32_t)h2 | ((uint32_t)h3<<16));
    uint2 lv = make_uint2((uint32_t)l0 | ((uint32_t)l1<<16), (uint32_t)l2 | ((uint32_t)l3<<16));
    reinterpret_cast<uint2*>(oh + (size_t)row*DD)[threadIdx.x] = hv;
    reinterpret_cast<uint2*>(ol + (size_t)row*DD)[threadIdx.x] = lv;
}

// ---------------- elementwise fp32 -> bf16 hi/lo split ----------------
__global__ __launch_bounds__(256) void split_vec(const float* __restrict__ in,
                                                 __nv_bfloat16* __restrict__ oh,
                                                 __nv_bfloat16* __restrict__ ol)
{
    size_t i = (size_t)blockIdx.x * 256 + threadIdx.x;
    float4 v = reinterpret_cast<const float4*>(in)[i];
    unsigned short h0,h1,h2,h3, l0,l1,l2,l3;
    split1(v.x,h0,l0); split1(v.y,h1,l1); split1(v.z,h2,l2); split1(v.w,h3,l3);
    reinterpret_cast<uint2*>(oh)[i] = make_uint2((uint32_t)h0 | ((uint32_t)h1<<16), (uint32_t)h2 | ((uint32_t)h3<<16));
    reinterpret_cast<uint2*>(ol)[i] = make_uint2((uint32_t)l0 | ((uint32_t)l1<<16), (uint32_t)l2 | ((uint32_t)l3<<16));
}

// ---------------- weight transpose + split: W[K,N] -> Bt[N,K] bf16 hi/lo ----------------
__global__ __launch_bounds__(256) void wsplit_t(const float* __restrict__ W,
                                                __nv_bfloat16* __restrict__ Bh,
                                                __nv_bfloat16* __restrict__ Bl,
                                                int K, int N)
{
    __shared__ float t[32][33];
    int n0 = blockIdx.x * 32, k0 = blockIdx.y * 32;
    int tx = threadIdx.x & 31, ty = threadIdx.x >> 5;   // ty 0..7
    #pragma unroll
    for (int r = 0; r < 4; r++)
        t[ty + 8*r][tx] = W[(size_t)(k0 + ty + 8*r) * N + n0 + tx];
    __syncthreads();
    #pragma unroll
    for (int r = 0; r < 4; r++) {
        int n = ty + 8*r, k = tx;
        float x = t[k][n];
        unsigned short h, l;
        split1(x, h, l);
        size_t o = (size_t)(n0 + n) * K + k0 + k;
        Bh[o] = __ushort_as_bfloat16(h);
        Bl[o] = __ushort_as_bfloat16(l);
    }
}

// ---------------- concat q/k/v biases ----------------
__global__ void bias3(const float* a, const float* b, const float* c, float* o) {
    int i = blockIdx.x * 256 + threadIdx.x;
    o[i] = (i < DD) ? a[i] : (i < 2*DD) ? b[i - DD] : c[i - 2*DD];
}

// ---------------- split-bf16 warp-MMA GEMM ----------------
// C[M,N] = A[M,K] @ Bt[N,K]^T, fp32 accum; 3 products: AhBh + AhBl + AlBh.
// CTA tile 128x128x32, 8 warps (2M x 4N), warp tile 64x32, m16n8k16.
#define MBK 32
#define SOFF_AHI 0
#define SOFF_ALO 8192
#define SOFF_BHI 16384
#define SOFF_BLO 24576
#define MSTAGE 32768
#define MSMEM (2*MSTAGE)

#define MODE_QKV3       1
#define MODE_RESID      2
#define MODE_RELU_SPLIT 3

__global__ __launch_bounds__(256, 1) void gemm_mma(
    const __nv_bfloat16* __restrict__ Ah, const __nv_bfloat16* __restrict__ Al,
    const __nv_bfloat16* __restrict__ Bh, const __nv_bfloat16* __restrict__ Bl,
    const float* __restrict__ bias, const float* __restrict__ resid,
    float* __restrict__ Cf, __nv_bfloat16* __restrict__ Ch, __nv_bfloat16* __restrict__ Cl,
    int M, int K, int N, int mode)
{
    extern __shared__ char smraw[];
    const uint32_t smbase = smem_u32(smraw);

    const int tid  = threadIdx.x;
    const int warp = tid >> 5;
    const int lane = tid & 31;
    const int warpMoff = (warp & 1) * 64;
    const int warpNoff = (warp >> 1) * 32;
    const int mBase = blockIdx.y * 128;
    const int nBase = blockIdx.x * 128;
    const int nk = K / MBK;

    // precompute per-thread ldmatrix swizzled offsets
    const int g = lane >> 3, l8 = lane & 7;
    uint32_t aoff[2][4], boff[2][2];
    #pragma unroll
    for (int ks = 0; ks < 2; ks++) {
        #pragma unroll
        for (int mt = 0; mt < 4; mt++)
            aoff[ks][mt] = tile_off(warpMoff + mt*16 + (g & 1)*8 + l8, 2*ks + (g >> 1));
        #pragma unroll
        for (int p = 0; p < 2; p++)
            boff[ks][p]  = tile_off(warpNoff + p*16 + (g >> 1)*8 + l8, 2*ks + (g & 1));
    }

    auto load_stage = [&](int chunk, int s) {
        const int k0 = chunk * MBK;
        uint32_t sb = smbase + (uint32_t)s * MSTAGE;
        #pragma unroll
        for (int h = 0; h < 2; h++) {
            int id = tid + h * 256;
            int r = id >> 2, c = id & 3;
            uint32_t so = tile_off(r, c);
            size_t ga = ((size_t)(mBase + r) * K + k0 + c*8) * 2;
            size_t gb = ((size_t)(nBase + r) * K + k0 + c*8) * 2;
            cp16(sb + SOFF_AHI + so, (const char*)Ah + ga);
            cp16(sb + SOFF_ALO + so, (const char*)Al + ga);
            cp16(sb + SOFF_BHI + so, (const char*)Bh + gb);
            cp16(sb + SOFF_BLO + so, (const char*)Bl + gb);
        }
        cp_commit();
    };

    load_stage(0, 0);
    load_stage(1, 1);

    float acc[4][4][4];
    #pragma unroll
    for (int mt = 0; mt < 4; mt++)
        #pragma unroll
        for (int nt = 0; nt < 4; nt++)
            #pragma unroll
            for (int e = 0; e < 4; e++) acc[mt][nt][e] = 0.f;

    for (int chunk = 0; chunk < nk; chunk++) {
        const int s = chunk & 1;
        if (chunk + 1 < nk) asm volatile("cp.async.wait_group 1;" ::: "memory");
        else                asm volatile("cp.async.wait_group 0;" ::: "memory");
        __syncthreads();

        const uint32_t sb = smbase + (uint32_t)s * MSTAGE;
        #pragma unroll
        for (int ks = 0; ks < 2; ks++) {
            uint32_t ahi[4][4], alo[4][4], bhi[4][2], blo[4][2];
            #pragma unroll
            for (int mt = 0; mt < 4; mt++) {
                ldsm4(ahi[mt], sb + SOFF_AHI + aoff[ks][mt]);
                ldsm4(alo[mt], sb + SOFF_ALO + aoff[ks][mt]);
            }
            #pragma unroll
            for (int p = 0; p < 2; p++) {
                ldsm4(&bhi[2*p][0], sb + SOFF_BHI + boff[ks][p]);
                ldsm4(&blo[2*p][0], sb + SOFF_BLO + boff[ks][p]);
            }
            #pragma unroll
            for (int nt = 0; nt < 4; nt++)
                #pragma unroll
                for (int mt = 0; mt < 4; mt++) {
                    mma_bf16(acc[mt][nt], ahi[mt], bhi[nt]);
                    mma_bf16(acc[mt][nt], ahi[mt], blo[nt]);
                    mma_bf16(acc[mt][nt], alo[mt], bhi[nt]);
                }
        }
        __syncthreads();
        if (chunk + 2 < nk) load_stage(chunk + 2, s);
    }

    // ---------------- epilogue ----------------
    const int rl = lane >> 2;
    const int cl = (lane & 3) * 2;

    #pragma unroll
    for (int mt = 0; mt < 4; mt++) {
        #pragma unroll
        for (int nt = 0; nt < 4; nt++) {
            int gr0 = mBase + warpMoff + mt*16 + rl;
            int gc  = nBase + warpNoff + nt*8 + cl;
            float b0 = __ldg(&bias[gc]);
            float b1 = __ldg(&bias[gc + 1]);
            float v00 = acc[mt][nt][0] + b0, v01 = acc[mt][nt][1] + b1;
            float v10 = acc[mt][nt][2] + b0, v11 = acc[mt][nt][3] + b1;

            if (mode == MODE_QKV3) {
                int t = gc >> 10;
                int within = gc & 1023;
                int h = within >> 6, jj = within & 63;
                #pragma unroll
                for (int rr = 0; rr < 2; rr++) {
                    int row = gr0 + rr*8;
                    int b = row >> 11, sI = row & 2047;
                    float* p = Cf + (size_t)t * NN * DD +
                               ((size_t)((b*HH + h)*SS + sI)) * HD + jj;
                    float2 o = rr ? make_float2(v10, v11) : make_float2(v00, v01);
                    *reinterpret_cast<float2*>(p) = o;
                }
            } else if (mode == MODE_RESID) {
                #pragma unroll
                for (int rr = 0; rr < 2; rr++) {
                    int row = gr0 + rr*8;
                    size_t ob = (size_t)row * N + gc;
                    float2 rv = *reinterpret_cast<const float2*>(resid + ob);
                    float2 o = rr ? make_float2(v10 + rv.x, v11 + rv.y)
                                  : make_float2(v00 + rv.x, v01 + rv.y);
                    *reinterpret_cast<float2*>(Cf + ob) = o;
                }
            } else { // MODE_RELU_SPLIT
                #pragma unroll
                for (int rr = 0; rr < 2; rr++) {
                    int row = gr0 + rr*8;
                    size_t ob = (size_t)row * N + gc;
                    float w0 = fmaxf(rr ? v10 : v00, 0.f);
                    float w1 = fmaxf(rr ? v11 : v01, 0.f);
                    unsigned short h0,l0,h1,l1;
                    split1(w0, h0, l0);
                    split1(w1, h1, l1);
                    reinterpret_cast<uint32_t*>(Ch)[ob >> 1] = (uint32_t)h0 | ((uint32_t)h1 << 16);
                    reinterpret_cast<uint32_t*>(Cl)[ob >> 1] = (uint32_t)l0 | ((uint32_t)l1 << 16);
                }
            }
        }
    }
}

// ---------------- RoPE (in place on [B,H,S,hd]); scale applied after rotation ----------------
__global__ __launch_bounds__(256) void rope_kernel(float* __restrict__ t, float scale)
{
    int idx = blockIdx.x * blockDim.x + threadIdx.x;
    int p = idx & 31;
    int s = (idx >> 5) & (SS - 1);
    float2 v = reinterpret_cast<float2*>(t)[idx];
    float inv = powf(10000.0f, -(float)p / 32.0f);
    float a = (float)s * inv;
    float sn, cs;
    sincosf(a, &sn, &cs);
    float x0 = v.x * cs - v.y * sn;
    float x1 = v.x * sn + v.y * cs;
    reinterpret_cast<float2*>(t)[idx] = make_float2(x0 * scale, x1 * scale);
}

// ---------------- Flash attention fp32 ----------------
#define ATTN_SMEM (4 * 64 * 68 * 4)

__global__ __launch_bounds__(256) void attn_kernel(const float* __restrict__ Q,
                                                   const float* __restrict__ Kg,
                                                   const float* __restrict__ V,
                                                   float* __restrict__ Out)
{
    extern __shared__ float sm[];
    float (*QsT)[68] = reinterpret_cast<float(*)[68]>(sm);
    float (*KsT)[68] = reinterpret_cast<float(*)[68]>(sm + 64*68);
    float (*Vs) [68] = reinterpret_cast<float(*)[68]>(sm + 2*64*68);
    float (*Ps) [68] = reinterpret_cast<float(*)[68]>(sm + 3*64*68);

    const int bh = blockIdx.y;
    const int q0 = blockIdx.x * 64;
    const int tid = threadIdx.x;
    const int tx = tid & 15, ty = tid >> 4;

    const float* Qb = Q  + ((size_t)bh * SS + q0) * HD;
    const float* Kb = Kg + (size_t)bh * SS * HD;
    const float* Vb = V  + (size_t)bh * SS * HD;

    {
        int r  = tid >> 2;
        int c0 = (tid & 3) * 16;
        #pragma unroll
        for (int u = 0; u < 4; u++) {
            float4 v4 = *reinterpret_cast<const float4*>(Qb + (size_t)r*HD + c0 + u*4);
            QsT[c0+u*4+0][r] = v4.x;
            QsT[c0+u*4+1][r] = v4.y;
            QsT[c0+u*4+2][r] = v4.z;
            QsT[c0+u*4+3][r] = v4.w;
        }
    }

    float m[4], l[4], acc[4][4];
    #pragma unroll
    for (int i = 0; i < 4; i++) {
        m[i] = -1e30f; l[i] = 0.f;
        #pragma unroll
        for (int j = 0; j < 4; j++) acc[i][j] = 0.f;
    }

    for (int kb = 0; kb < SS; kb += 64) {
        __syncthreads();
        {
            int r  = tid >> 2;
            int c0 = (tid & 3) * 16;
            #pragma unroll
            for (int u = 0; u < 4; u++) {
                float4 kv = *reinterpret_cast<const float4*>(Kb + (size_t)(kb + r)*HD + c0 + u*4);
                KsT[c0+u*4+0][r] = kv.x;
                KsT[c0+u*4+1][r] = kv.y;
                KsT[c0+u*4+2][r] = kv.z;
                KsT[c0+u*4+3][r] = kv.w;
                float4 vv = *reinterpret_cast<const float4*>(Vb + (size_t)(kb + r)*HD + c0 + u*4);
                *reinterpret_cast<float4*>(&Vs[r][c0+u*4]) = vv;
            }
        }
        __syncthreads();

        float s4[4][4];
        #pragma unroll
        for (int i = 0; i < 4; i++)
            #pragma unroll
            for (int j = 0; j < 4; j++) s4[i][j] = 0.f;

        #pragma unroll 8
        for (int kk = 0; kk < 64; kk++) {
            float4 qa = *reinterpret_cast<const float4*>(&QsT[kk][ty*4]);
            float4 ka = *reinterpret_cast<const float4*>(&KsT[kk][tx*4]);
            float ra[4] = {qa.x, qa.y, qa.z, qa.w};
            float rb[4] = {ka.x, ka.y, ka.z, ka.w};
            #pragma unroll
            for (int i = 0; i < 4; i++)
                #pragma unroll
                for (int j = 0; j < 4; j++)
                    s4[i][j] += ra[i] * rb[j];
        }

        #pragma unroll
        for (int i = 0; i < 4; i++) {
            float mx = fmaxf(fmaxf(s4[i][0], s4[i][1]), fmaxf(s4[i][2], s4[i][3]));
            #pragma unroll
            for (int o = 1; o < 16; o <<= 1)
                mx = fmaxf(mx, __shfl_xor_sync(0xffffffffu, mx, o));
            float mnew  = fmaxf(m[i], mx);
            float alpha = __expf(m[i] - mnew);
            float rs = 0.f;
            #pragma unroll
            for (int j = 0; j < 4; j++) {
                s4[i][j] = __expf(s4[i][j] - mnew);
                rs += s4[i][j];
            }
            #pragma unroll
            for (int o = 1; o < 16; o <<= 1)
                rs += __shfl_xor_sync(0xffffffffu, rs, o);
            l[i] = l[i] * alpha + rs;
            m[i] = mnew;
            #pragma unroll
            for (int j = 0; j < 4; j++) acc[i][j] *= alpha;
        }

        #pragma unroll
        for (int i = 0; i < 4; i++)
            *reinterpret_cast<float4*>(&Ps[ty*4+i][tx*4]) =
                make_float4(s4[i][0], s4[i][1], s4[i][2], s4[i][3]);
        __syncthreads();

        #pragma unroll 4
        for (int kk = 0; kk < 64; kk += 4) {
            float pr[4][4];
            #pragma unroll
            for (int i = 0; i < 4; i++) {
                float4 t4 = *reinterpret_cast<const float4*>(&Ps[ty*4+i][kk]);
                pr[i][0] = t4.x; pr[i][1] = t4.y; pr[i][2] = t4.z; pr[i][3] = t4.w;
            }
            #pragma unroll
            for (int u = 0; u < 4; u++) {
                float4 vv = *reinterpret_cast<const float4*>(&Vs[kk+u][tx*4]);
                #pragma unroll
                for (int i = 0; i < 4; i++) {
                    acc[i][0] += pr[i][u] * vv.x;
                    acc[i][1] += pr[i][u] * vv.y;
                    acc[i][2] += pr[i][u] * vv.z;
                    acc[i][3] += pr[i][u] * vv.w;
                }
            }
        }
    }

    int b = bh >> 4, h = bh & 15;
    #pragma unroll
    for (int i = 0; i < 4; i++) {
        int srow = q0 + ty*4 + i;
        float inv = 1.f / l[i];
        float4 o = make_float4(acc[i][0]*inv, acc[i][1]*inv, acc[i][2]*inv, acc[i][3]*inv);
        *reinterpret_cast<float4*>(&Out[((size_t)(b*SS + srow))*DD + h*HD + tx*4]) = o;
    }
}

// ---------------- host launch ----------------
extern "C" void kernel_launch(void* const* d_in, const int* in_sizes, int n_in,
                              void* d_out, int out_size)
{
    const float* x     = (const float*)d_in[0];
    const float* Wq    = (const float*)d_in[1];
    const float* bq    = (const float*)d_in[2];
    const float* Wk    = (const float*)d_in[3];
    const float* bk    = (const float*)d_in[4];
    const float* Wv    = (const float*)d_in[5];
    const float* bv    = (const float*)d_in[6];
    const float* Wo    = (const float*)d_in[7];
    const float* bo    = (const float*)d_in[8];
    const float* W1    = (const float*)d_in[9];
    const float* b1    = (const float*)d_in[10];
    const float* W2    = (const float*)d_in[11];
    const float* b2    = (const float*)d_in[12];
    const float* g1    = (const float*)d_in[13];
    const float* beta1 = (const float*)d_in[14];
    const float* g2    = (const float*)d_in[15];
    const float* beta2 = (const float*)d_in[16];
    float* out = (float*)d_out;

    float *qkv, *attn, *x1, *bqkv;
    __nv_bfloat16 *xnh, *xnl, *xn2h, *xn2l, *ath, *atl, *hh, *hl;
    __nv_bfloat16 *qkvth, *qkvtl, *woth, *wotl, *w1th, *w1tl, *w2th, *w2tl;
    cudaGetSymbolAddress((void**)&qkv,   g_qkv);
    cudaGetSymbolAddress((void**)&attn,  g_attn);
    cudaGetSymbolAddress((void**)&x1,    g_x1);
    cudaGetSymbolAddress((void**)&bqkv,  g_bqkv);
    cudaGetSymbolAddress((void**)&xnh,   g_xn_h);
    cudaGetSymbolAddress((void**)&xnl,   g_xn_l);
    cudaGetSymbolAddress((void**)&xn2h,  g_xn2_h);
    cudaGetSymbolAddress((void**)&xn2l,  g_xn2_l);
    cudaGetSymbolAddress((void**)&ath,   g_at_h);
    cudaGetSymbolAddress((void**)&atl,   g_at_l);
    cudaGetSymbolAddress((void**)&hh,    g_h_h);
    cudaGetSymbolAddress((void**)&hl,    g_h_l);
    cudaGetSymbolAddress((void**)&qkvth, g_qkvt_h);
    cudaGetSymbolAddress((void**)&qkvtl, g_qkvt_l);
    cudaGetSymbolAddress((void**)&woth,  g_wot_h);
    cudaGetSymbolAddress((void**)&wotl,  g_wot_l);
    cudaGetSymbolAddress((void**)&w1th,  g_w1t_h);
    cudaGetSymbolAddress((void**)&w1tl,  g_w1t_l);
    cudaGetSymbolAddress((void**)&w2th,  g_w2t_h);
    cudaGetSymbolAddress((void**)&w2tl,  g_w2t_l);

    cudaFuncSetAttribute(gemm_mma, cudaFuncAttributeMaxDynamicSharedMemorySize, MSMEM);
    cudaFuncSetAttribute(attn_kernel, cudaFuncAttributeMaxDynamicSharedMemorySize, ATTN_SMEM);

    // weight prep: transpose + hi/lo split
    wsplit_t<<<dim3(DD/32, DD/32), 256>>>(Wq, qkvth,            qkvtl,            DD, DD);
    wsplit_t<<<dim3(DD/32, DD/32), 256>>>(Wk, qkvth + DD*DD,    qkvtl + DD*DD,    DD, DD);
    wsplit_t<<<dim3(DD/32, DD/32), 256>>>(Wv, qkvth + 2*DD*DD,  qkvtl + 2*DD*DD,  DD, DD);
    wsplit_t<<<dim3(DD/32, DD/32), 256>>>(Wo, woth, wotl, DD, DD);
    wsplit_t<<<dim3(FF/32, DD/32), 256>>>(W1, w1th, w1tl, DD, FF);
    wsplit_t<<<dim3(DD/32, FF/32), 256>>>(W2, w2th, w2tl, FF, DD);
    bias3<<<3*DD/256, 256>>>(bq, bk, bv, bqkv);

    // LN1 -> split
    ln_split<<<NN, 256>>>(x, g1, beta1, xnh, xnl);

    // fused QKV projection (N=3072), scatter epilogue
    gemm_mma<<<dim3(3*DD/128, NN/128), 256, MSMEM>>>(
        xnh, xnl, qkvth, qkvtl, bqkv, nullptr, qkv, nullptr, nullptr,
        NN, DD, 3*DD, MODE_QKV3);

    float* q = qkv;
    float* k = qkv + (size_t)NN*DD;
    float* v = qkv + 2*(size_t)NN*DD;

    int ropeBlocks = (BB*HH*SS*(HD/2)) / 256;
    rope_kernel<<<ropeBlocks, 256>>>(q, 0.125f);
    rope_kernel<<<ropeBlocks, 256>>>(k, 1.0f);

    attn_kernel<<<dim3(SS/64, BB*HH), 256, ATTN_SMEM>>>(q, k, v, attn);

    // split attention output for Wo GEMM
    split_vec<<<(NN*DD/4)/256, 256>>>(attn, ath, atl);

    // x1 = x + attn @ Wo + bo
    gemm_mma<<<dim3(DD/128, NN/128), 256, MSMEM>>>(
        ath, atl, woth, wotl, bo, x, x1, nullptr, nullptr,
        NN, DD, DD, MODE_RESID);

    // LN2 -> split
    ln_split<<<NN, 256>>>(x1, g2, beta2, xn2h, xn2l);

    // FFN up: relu + split epilogue
    gemm_mma<<<dim3(FF/128, NN/128), 256, MSMEM>>>(
        xn2h, xn2l, w1th, w1tl, b1, nullptr, nullptr, hh, hl,
        NN, DD, FF, MODE_RELU_SPLIT);

    // FFN down + residual -> out
    gemm_mma<<<dim3(DD/128, NN/128), 256, MSMEM>>>(
        hh, hl, w2th, w2tl, b2, x1, out, nullptr, nullptr,
        NN, FF, DD, MODE_RESID);
}

// round 6
// speedup vs baseline: 2.9032x; 1.5535x over previous
#include <cuda_runtime.h>
#include <cuda_bf16.h>
#include <math.h>
#include <stdint.h>

#define BB 2
#define SS 2048
#define DD 1024
#define HH 16
#define HD 64
#define FF 4096
#define NN (BB*SS)   // 4096 tokens

// ---------------- scratch (static device globals; no allocs) ----------------
__device__ float g_qkv [3u*NN*DD];   // q,k,v each [B,H,S,hd] fp32
__device__ float g_x1  [NN*DD];      // x + attn_out
__device__ __nv_bfloat16 g_xn_h [NN*DD], g_xn_l [NN*DD];
__device__ __nv_bfloat16 g_xn2_h[NN*DD], g_xn2_l[NN*DD];
__device__ __nv_bfloat16 g_at_h [NN*DD], g_at_l [NN*DD];   // attn out [B,S,D]
__device__ __nv_bfloat16 g_q_h  [NN*DD], g_q_l  [NN*DD];   // [B,H,S,hd]
__device__ __nv_bfloat16 g_k_h  [NN*DD], g_k_l  [NN*DD];   // [B,H,S,hd]
__device__ __nv_bfloat16 g_vt_h [NN*DD], g_vt_l [NN*DD];   // [B,H,hd,S]
__device__ __nv_bfloat16 g_h_h  [(size_t)NN*FF], g_h_l[(size_t)NN*FF];
__device__ __nv_bfloat16 g_qkvt_h[3*DD*DD], g_qkvt_l[3*DD*DD]; // [3072,1024]
__device__ __nv_bfloat16 g_wot_h [DD*DD],   g_wot_l [DD*DD];
__device__ __nv_bfloat16 g_w1t_h [FF*DD],   g_w1t_l [FF*DD];
__device__ __nv_bfloat16 g_w2t_h [DD*FF],   g_w2t_l [DD*FF];
__device__ float g_bqkv[3*DD];

// ---------------- helpers ----------------
__device__ __forceinline__ uint32_t smem_u32(const void* p) {
    return (uint32_t)__cvta_generic_to_shared(p);
}
__device__ __forceinline__ void cp16(uint32_t s, const void* g) {
    asm volatile("cp.async.cg.shared.global [%0], [%1], 16;" :: "r"(s), "l"(g));
}
__device__ __forceinline__ void cp_commit() {
    asm volatile("cp.async.commit_group;" ::: "memory");
}
__device__ __forceinline__ void ldsm4(uint32_t* r, uint32_t addr) {
    asm volatile("ldmatrix.sync.aligned.m8n8.x4.shared.b16 {%0,%1,%2,%3}, [%4];"
        : "=r"(r[0]), "=r"(r[1]), "=r"(r[2]), "=r"(r[3]) : "r"(addr));
}
__device__ __forceinline__ void mma_bf16(float* d, const uint32_t* a, const uint32_t* b) {
    asm volatile("mma.sync.aligned.m16n8k16.row.col.f32.bf16.bf16.f32 "
        "{%0,%1,%2,%3}, {%4,%5,%6,%7}, {%8,%9}, {%0,%1,%2,%3};"
        : "+f"(d[0]), "+f"(d[1]), "+f"(d[2]), "+f"(d[3])
        : "r"(a[0]), "r"(a[1]), "r"(a[2]), "r"(a[3]), "r"(b[0]), "r"(b[1]));
}
__device__ __forceinline__ void split1(float x, unsigned short& h, unsigned short& l) {
    __nv_bfloat16 hb = __float2bfloat16(x);
    float hf = __bfloat162float(hb);
    __nv_bfloat16 lb = __float2bfloat16(x - hf);
    h = __bfloat16_as_ushort(hb);
    l = __bfloat16_as_ushort(lb);
}
// swizzled offset inside a R-row x 64B tile: (row, 16B-chunk c in 0..3)
__device__ __forceinline__ uint32_t tile_off(int r, int c) {
    return (uint32_t)(((r >> 1) * 128) + (((((r & 1) << 2) | c) ^ ((r >> 1) & 7)) << 4));
}

// ---------------- LayerNorm with bf16 hi/lo split output ----------------
__global__ __launch_bounds__(256) void ln_split(const float* __restrict__ x,
                                                const float* __restrict__ gamma,
                                                const float* __restrict__ beta,
                                                __nv_bfloat16* __restrict__ oh,
                                                __nv_bfloat16* __restrict__ ol)
{
    int row = blockIdx.x;
    const float4* xr = reinterpret_cast<const float4*>(x + (size_t)row * DD);
    float4 v = xr[threadIdx.x];

    float s  = v.x + v.y + v.z + v.w;
    float sq = v.x*v.x + v.y*v.y + v.z*v.z + v.w*v.w;
    #pragma unroll
    for (int o = 16; o > 0; o >>= 1) {
        s  += __shfl_xor_sync(0xffffffffu, s,  o);
        sq += __shfl_xor_sync(0xffffffffu, sq, o);
    }
    __shared__ float ps[8], psq[8];
    int wid = threadIdx.x >> 5, lane = threadIdx.x & 31;
    if (lane == 0) { ps[wid] = s; psq[wid] = sq; }
    __syncthreads();
    float ts = 0.f, tsq = 0.f;
    #pragma unroll
    for (int i = 0; i < 8; i++) { ts += ps[i]; tsq += psq[i]; }

    float mu   = ts * (1.0f / DD);
    float var  = tsq * (1.0f / DD) - mu * mu;
    float rstd = rsqrtf(var + 1e-5f);

    float4 g = reinterpret_cast<const float4*>(gamma)[threadIdx.x];
    float4 b = reinterpret_cast<const float4*>(beta )[threadIdx.x];
    float o0 = (v.x - mu) * rstd * g.x + b.x;
    float o1 = (v.y - mu) * rstd * g.y + b.y;
    float o2 = (v.z - mu) * rstd * g.z + b.z;
    float o3 = (v.w - mu) * rstd * g.w + b.w;

    unsigned short h0,h1,h2,h3, l0,l1,l2,l3;
    split1(o0,h0,l0); split1(o1,h1,l1); split1(o2,h2,l2); split1(o3,h3,l3);
    uint2 hv = make_uint2((uint32_t)h0 | ((uint32_t)h1<<16), (uint32_t)h2 | ((uint32_t)h3<<16));
    uint2 lv = make_uint2((uint32_t)l0 | ((uint32_t)l1<<16), (uint32_t)l2 | ((uint32_t)l3<<16));
    reinterpret_cast<uint2*>(oh + (size_t)row*DD)[threadIdx.x] = hv;
    reinterpret_cast<uint2*>(ol + (size_t)row*DD)[threadIdx.x] = lv;
}

// ---------------- weight transpose + split: W[K,N] -> Bt[N,K] bf16 hi/lo ----------------
__global__ __launch_bounds__(256) void wsplit_t(const float* __restrict__ W,
                                                __nv_bfloat16* __restrict__ Bh,
                                                __nv_bfloat16* __restrict__ Bl,
                                                int K, int N)
{
    __shared__ float t[32][33];
    int n0 = blockIdx.x * 32, k0 = blockIdx.y * 32;
    int tx = threadIdx.x & 31, ty = threadIdx.x >> 5;
    #pragma unroll
    for (int r = 0; r < 4; r++)
        t[ty + 8*r][tx] = W[(size_t)(k0 + ty + 8*r) * N + n0 + tx];
    __syncthreads();
    #pragma unroll
    for (int r = 0; r < 4; r++) {
        int n = ty + 8*r, k = tx;
        float x = t[k][n];
        unsigned short h, l;
        split1(x, h, l);
        size_t o = (size_t)(n0 + n) * K + k0 + k;
        Bh[o] = __ushort_as_bfloat16(h);
        Bl[o] = __ushort_as_bfloat16(l);
    }
}

// ---------------- concat q/k/v biases ----------------
__global__ void bias3(const float* a, const float* b, const float* c, float* o) {
    int i = blockIdx.x * 256 + threadIdx.x;
    o[i] = (i < DD) ? a[i] : (i < 2*DD) ? b[i - DD] : c[i - 2*DD];
}

// ---------------- RoPE + split: fp32 [B,H,S,hd] -> bf16 hi/lo same layout ----------------
__global__ __launch_bounds__(256) void rope_split(const float* __restrict__ t,
                                                  __nv_bfloat16* __restrict__ oh,
                                                  __nv_bfloat16* __restrict__ ol,
                                                  float scale)
{
    int idx = blockIdx.x * blockDim.x + threadIdx.x;   // pair index
    int p = idx & 31;
    int s = (idx >> 5) & (SS - 1);
    float2 v = reinterpret_cast<const float2*>(t)[idx];
    float inv = powf(10000.0f, -(float)p / 32.0f);
    float a = (float)s * inv;
    float sn, cs;
    sincosf(a, &sn, &cs);
    float x0 = (v.x * cs - v.y * sn) * scale;
    float x1 = (v.x * sn + v.y * cs) * scale;
    unsigned short h0,l0,h1,l1;
    split1(x0,h0,l0); split1(x1,h1,l1);
    reinterpret_cast<uint32_t*>(oh)[idx] = (uint32_t)h0 | ((uint32_t)h1 << 16);
    reinterpret_cast<uint32_t*>(ol)[idx] = (uint32_t)l0 | ((uint32_t)l1 << 16);
}

// ---------------- V transpose + split: fp32 [B,H,S,hd] -> bf16 hi/lo [B,H,hd,S] ----------------
__global__ __launch_bounds__(256) void vsplit_t(const float* __restrict__ v,
                                                __nv_bfloat16* __restrict__ vth,
                                                __nv_bfloat16* __restrict__ vtl)
{
    __shared__ float t[32][33];
    int bh = blockIdx.z;
    int s0 = blockIdx.x * 32, d0 = blockIdx.y * 32;
    int tx = threadIdx.x & 31, ty = threadIdx.x >> 5;
    #pragma unroll
    for (int r = 0; r < 4; r++)
        t[ty + 8*r][tx] = v[((size_t)bh * SS + s0 + ty + 8*r) * HD + d0 + tx];
    __syncthreads();
    #pragma unroll
    for (int r = 0; r < 4; r++) {
        int d = ty + 8*r, s = tx;
        float x = t[s][d];
        unsigned short h, l;
        split1(x, h, l);
        size_t o = ((size_t)bh * HD + d0 + d) * SS + s0 + s;
        vth[o] = __ushort_as_bfloat16(h);
        vtl[o] = __ushort_as_bfloat16(l);
    }
}

// ---------------- split-bf16 warp-MMA GEMM (unchanged from R4) ----------------
#define MBK 32
#define SOFF_AHI 0
#define SOFF_ALO 8192
#define SOFF_BHI 16384
#define SOFF_BLO 24576
#define MSTAGE 32768
#define MSMEM (2*MSTAGE)

#define MODE_QKV3       1
#define MODE_RESID      2
#define MODE_RELU_SPLIT 3

__global__ __launch_bounds__(256, 1) void gemm_mma(
    const __nv_bfloat16* __restrict__ Ah, const __nv_bfloat16* __restrict__ Al,
    const __nv_bfloat16* __restrict__ Bh, const __nv_bfloat16* __restrict__ Bl,
    const float* __restrict__ bias, const float* __restrict__ resid,
    float* __restrict__ Cf, __nv_bfloat16* __restrict__ Ch, __nv_bfloat16* __restrict__ Cl,
    int M, int K, int N, int mode)
{
    extern __shared__ char smraw[];
    const uint32_t smbase = smem_u32(smraw);

    const int tid  = threadIdx.x;
    const int warp = tid >> 5;
    const int lane = tid & 31;
    const int warpMoff = (warp & 1) * 64;
    const int warpNoff = (warp >> 1) * 32;
    const int mBase = blockIdx.y * 128;
    const int nBase = blockIdx.x * 128;
    const int nk = K / MBK;

    const int g = lane >> 3, l8 = lane & 7;
    uint32_t aoff[2][4], boff[2][2];
    #pragma unroll
    for (int ks = 0; ks < 2; ks++) {
        #pragma unroll
        for (int mt = 0; mt < 4; mt++)
            aoff[ks][mt] = tile_off(warpMoff + mt*16 + (g & 1)*8 + l8, 2*ks + (g >> 1));
        #pragma unroll
        for (int p = 0; p < 2; p++)
            boff[ks][p]  = tile_off(warpNoff + p*16 + (g >> 1)*8 + l8, 2*ks + (g & 1));
    }

    auto load_stage = [&](int chunk, int s) {
        const int k0 = chunk * MBK;
        uint32_t sb = smbase + (uint32_t)s * MSTAGE;
        #pragma unroll
        for (int h = 0; h < 2; h++) {
            int id = tid + h * 256;
            int r = id >> 2, c = id & 3;
            uint32_t so = tile_off(r, c);
            size_t ga = ((size_t)(mBase + r) * K + k0 + c*8) * 2;
            size_t gb = ((size_t)(nBase + r) * K + k0 + c*8) * 2;
            cp16(sb + SOFF_AHI + so, (const char*)Ah + ga);
            cp16(sb + SOFF_ALO + so, (const char*)Al + ga);
            cp16(sb + SOFF_BHI + so, (const char*)Bh + gb);
            cp16(sb + SOFF_BLO + so, (const char*)Bl + gb);
        }
        cp_commit();
    };

    load_stage(0, 0);
    load_stage(1, 1);

    float acc[4][4][4];
    #pragma unroll
    for (int mt = 0; mt < 4; mt++)
        #pragma unroll
        for (int nt = 0; nt < 4; nt++)
            #pragma unroll
            for (int e = 0; e < 4; e++) acc[mt][nt][e] = 0.f;

    for (int chunk = 0; chunk < nk; chunk++) {
        const int s = chunk & 1;
        if (chunk + 1 < nk) asm volatile("cp.async.wait_group 1;" ::: "memory");
        else                asm volatile("cp.async.wait_group 0;" ::: "memory");
        __syncthreads();

        const uint32_t sb = smbase + (uint32_t)s * MSTAGE;
        #pragma unroll
        for (int ks = 0; ks < 2; ks++) {
            uint32_t ahi[4][4], alo[4][4], bhi[4][2], blo[4][2];
            #pragma unroll
            for (int mt = 0; mt < 4; mt++) {
                ldsm4(ahi[mt], sb + SOFF_AHI + aoff[ks][mt]);
                ldsm4(alo[mt], sb + SOFF_ALO + aoff[ks][mt]);
            }
            #pragma unroll
            for (int p = 0; p < 2; p++) {
                ldsm4(&bhi[2*p][0], sb + SOFF_BHI + boff[ks][p]);
                ldsm4(&blo[2*p][0], sb + SOFF_BLO + boff[ks][p]);
            }
            #pragma unroll
            for (int nt = 0; nt < 4; nt++)
                #pragma unroll
                for (int mt = 0; mt < 4; mt++) {
                    mma_bf16(acc[mt][nt], ahi[mt], bhi[nt]);
                    mma_bf16(acc[mt][nt], ahi[mt], blo[nt]);
                    mma_bf16(acc[mt][nt], alo[mt], bhi[nt]);
                }
        }
        __syncthreads();
        if (chunk + 2 < nk) load_stage(chunk + 2, s);
    }

    const int rl = lane >> 2;
    const int cl = (lane & 3) * 2;

    #pragma unroll
    for (int mt = 0; mt < 4; mt++) {
        #pragma unroll
        for (int nt = 0; nt < 4; nt++) {
            int gr0 = mBase + warpMoff + mt*16 + rl;
            int gc  = nBase + warpNoff + nt*8 + cl;
            float b0 = __ldg(&bias[gc]);
            float b1 = __ldg(&bias[gc + 1]);
            float v00 = acc[mt][nt][0] + b0, v01 = acc[mt][nt][1] + b1;
            float v10 = acc[mt][nt][2] + b0, v11 = acc[mt][nt][3] + b1;

            if (mode == MODE_QKV3) {
                int t = gc >> 10;
                int within = gc & 1023;
                int h = within >> 6, jj = within & 63;
                #pragma unroll
                for (int rr = 0; rr < 2; rr++) {
                    int row = gr0 + rr*8;
                    int b = row >> 11, sI = row & 2047;
                    float* p = Cf + (size_t)t * NN * DD +
                               ((size_t)((b*HH + h)*SS + sI)) * HD + jj;
                    float2 o = rr ? make_float2(v10, v11) : make_float2(v00, v01);
                    *reinterpret_cast<float2*>(p) = o;
                }
            } else if (mode == MODE_RESID) {
                #pragma unroll
                for (int rr = 0; rr < 2; rr++) {
                    int row = gr0 + rr*8;
                    size_t ob = (size_t)row * N + gc;
                    float2 rv = *reinterpret_cast<const float2*>(resid + ob);
                    float2 o = rr ? make_float2(v10 + rv.x, v11 + rv.y)
                                  : make_float2(v00 + rv.x, v01 + rv.y);
                    *reinterpret_cast<float2*>(Cf + ob) = o;
                }
            } else { // MODE_RELU_SPLIT
                #pragma unroll
                for (int rr = 0; rr < 2; rr++) {
                    int row = gr0 + rr*8;
                    size_t ob = (size_t)row * N + gc;
                    float w0 = fmaxf(rr ? v10 : v00, 0.f);
                    float w1 = fmaxf(rr ? v11 : v01, 0.f);
                    unsigned short h0,l0,h1,l1;
                    split1(w0, h0, l0);
                    split1(w1, h1, l1);
                    reinterpret_cast<uint32_t*>(Ch)[ob >> 1] = (uint32_t)h0 | ((uint32_t)h1 << 16);
                    reinterpret_cast<uint32_t*>(Cl)[ob >> 1] = (uint32_t)l0 | ((uint32_t)l1 << 16);
                }
            }
        }
    }
}

// ---------------- split-bf16 MMA flash attention ----------------
// CTA: 128 queries x one (b,h); 8 warps x 16 rows. 64-key tiles, double buffer.
// smem: Qh[2 tiles 128x64B] Ql | stages { Kh, Kl (64x128B), Vth, Vtl (64x128B) }
#define AT_SQH   0
#define AT_SQL   16384
#define AT_STAGE 32768
#define AT_SSZ   32768
#define AT_KH    0
#define AT_KL    8192
#define AT_VH    16384
#define AT_VL    24576
#define ATTN_SMEM (32768 + 2*32768)

__global__ __launch_bounds__(256, 2) void attn_mma(
    const __nv_bfloat16* __restrict__ Qh, const __nv_bfloat16* __restrict__ Ql,
    const __nv_bfloat16* __restrict__ Kh, const __nv_bfloat16* __restrict__ Kl,
    const __nv_bfloat16* __restrict__ Vth, const __nv_bfloat16* __restrict__ Vtl,
    __nv_bfloat16* __restrict__ Oh, __nv_bfloat16* __restrict__ Ol)
{
    extern __shared__ char smraw[];
    const uint32_t sm = smem_u32(smraw);
    const int tid = threadIdx.x, warp = tid >> 5, lane = tid & 31;
    const int bh = blockIdx.y;
    const int q0 = blockIdx.x * 128;
    const int g = lane >> 3, l8 = lane & 7;
    const int rl = lane >> 2, cl = (lane & 3) * 2;

    // load Q tiles (hi/lo), part of first commit group
    #pragma unroll
    for (int t = 0; t < 8; t++) {
        int buf = t >> 2;                    // 0=hi,1=lo
        int w = (t & 3) * 256 + tid;         // 0..1023
        int r = w >> 3, c = w & 7;
        uint32_t off = (buf ? AT_SQL : AT_SQH) + (c >> 2) * 8192 + tile_off(r, c & 3);
        const char* gp = (const char*)(buf ? Ql : Qh) +
                         ((size_t)((size_t)bh * SS + q0 + r) * HD + c * 8) * 2;
        cp16(sm + off, gp);
    }

    auto load_kv = [&](int kb, int s) {
        uint32_t sb = sm + AT_STAGE + (uint32_t)s * AT_SSZ;
        #pragma unroll
        for (int t = 0; t < 8; t++) {
            int buf = t >> 1;                // 0=Kh 1=Kl 2=Vh 3=Vl
            int w = (t & 1) * 256 + tid;     // 0..511
            int r = w >> 3, c = w & 7;
            uint32_t off = (uint32_t)buf * 8192 + (c >> 2) * 4096 + tile_off(r, c & 3);
            const char* gp;
            if (buf == 0)      gp = (const char*)Kh  + ((size_t)((size_t)bh * SS + kb + r) * HD + c * 8) * 2;
            else if (buf == 1) gp = (const char*)Kl  + ((size_t)((size_t)bh * SS + kb + r) * HD + c * 8) * 2;
            else if (buf == 2) gp = (const char*)Vth + ((size_t)((size_t)bh * HD + r) * SS + kb + c * 8) * 2;
            else               gp = (const char*)Vtl + ((size_t)((size_t)bh * HD + r) * SS + kb + c * 8) * 2;
            cp16(sb + off, gp);
        }
        cp_commit();
    };

    load_kv(0, 0);    // group 0 = Q + stage0
    load_kv(64, 1);   // group 1 = stage1

    float m0 = -1e30f, m1 = -1e30f, l0 = 0.f, l1 = 0.f;
    float acc[8][4];
    #pragma unroll
    for (int nt = 0; nt < 8; nt++)
        #pragma unroll
        for (int e = 0; e < 4; e++) acc[nt][e] = 0.f;

    const int NT = SS / 64;   // 32
    for (int it = 0; it < NT; it++) {
        if (it + 1 < NT) asm volatile("cp.async.wait_group 1;" ::: "memory");
        else             asm volatile("cp.async.wait_group 0;" ::: "memory");
        __syncthreads();
        const uint32_t sb = sm + AT_STAGE + (uint32_t)(it & 1) * AT_SSZ;

        // ---- S = Q K^T (split 3-product) ----
        float sacc[8][4];
        #pragma unroll
        for (int nt = 0; nt < 8; nt++)
            #pragma unroll
            for (int e = 0; e < 4; e++) sacc[nt][e] = 0.f;

        #pragma unroll
        for (int ks = 0; ks < 4; ks++) {
            uint32_t qoff = (uint32_t)((ks >> 1) * 8192) +
                            tile_off(warp*16 + (g & 1)*8 + l8, 2*(ks & 1) + (g >> 1));
            uint32_t qh4[4], ql4[4];
            ldsm4(qh4, sm + AT_SQH + qoff);
            ldsm4(ql4, sm + AT_SQL + qoff);
            uint32_t kh4[4][4], kl4[4][4];
            #pragma unroll
            for (int p = 0; p < 4; p++) {
                uint32_t ko = (uint32_t)((ks >> 1) * 4096) +
                              tile_off(p*16 + (g >> 1)*8 + l8, 2*(ks & 1) + (g & 1));
                ldsm4(kh4[p], sb + AT_KH + ko);
                ldsm4(kl4[p], sb + AT_KL + ko);
            }
            #pragma unroll
            for (int nt = 0; nt < 8; nt++) {
                const uint32_t* bhk = &kh4[nt >> 1][(nt & 1) * 2];
                const uint32_t* blk = &kl4[nt >> 1][(nt & 1) * 2];
                mma_bf16(sacc[nt], qh4, bhk);
                mma_bf16(sacc[nt], qh4, blk);
                mma_bf16(sacc[nt], ql4, bhk);
            }
        }

        // ---- online softmax ----
        float mx0 = -1e30f, mx1 = -1e30f;
        #pragma unroll
        for (int nt = 0; nt < 8; nt++) {
            mx0 = fmaxf(mx0, fmaxf(sacc[nt][0], sacc[nt][1]));
            mx1 = fmaxf(mx1, fmaxf(sacc[nt][2], sacc[nt][3]));
        }
        mx0 = fmaxf(mx0, __shfl_xor_sync(0xffffffffu, mx0, 1));
        mx0 = fmaxf(mx0, __shfl_xor_sync(0xffffffffu, mx0, 2));
        mx1 = fmaxf(mx1, __shfl_xor_sync(0xffffffffu, mx1, 1));
        mx1 = fmaxf(mx1, __shfl_xor_sync(0xffffffffu, mx1, 2));

        float mn0 = fmaxf(m0, mx0), mn1 = fmaxf(m1, mx1);
        float a0 = __expf(m0 - mn0), a1 = __expf(m1 - mn1);
        float rs0 = 0.f, rs1 = 0.f;
        #pragma unroll
        for (int nt = 0; nt < 8; nt++) {
            sacc[nt][0] = __expf(sacc[nt][0] - mn0);
            sacc[nt][1] = __expf(sacc[nt][1] - mn0);
            sacc[nt][2] = __expf(sacc[nt][2] - mn1);
            sacc[nt][3] = __expf(sacc[nt][3] - mn1);
            rs0 += sacc[nt][0] + sacc[nt][1];
            rs1 += sacc[nt][2] + sacc[nt][3];
        }
        rs0 += __shfl_xor_sync(0xffffffffu, rs0, 1);
        rs0 += __shfl_xor_sync(0xffffffffu, rs0, 2);
        rs1 += __shfl_xor_sync(0xffffffffu, rs1, 1);
        rs1 += __shfl_xor_sync(0xffffffffu, rs1, 2);
        l0 = l0 * a0 + rs0;  m0 = mn0;
        l1 = l1 * a1 + rs1;  m1 = mn1;
        #pragma unroll
        for (int nt = 0; nt < 8; nt++) {
            acc[nt][0] *= a0; acc[nt][1] *= a0;
            acc[nt][2] *= a1; acc[nt][3] *= a1;
        }

        // ---- O += P V (split 3-product), P packed per k-step ----
        #pragma unroll
        for (int ks = 0; ks < 4; ks++) {
            uint32_t aH[4], aL[4];
            #pragma unroll
            for (int half = 0; half < 2; half++) {
                int nt = 2*ks + half;
                unsigned short h0,l0s,h1,l1s,h2,l2s,h3,l3s;
                split1(sacc[nt][0], h0, l0s);
                split1(sacc[nt][1], h1, l1s);
                split1(sacc[nt][2], h2, l2s);
                split1(sacc[nt][3], h3, l3s);
                aH[half*2 + 0] = (uint32_t)h0  | ((uint32_t)h1  << 16);
                aH[half*2 + 1] = (uint32_t)h2  | ((uint32_t)h3  << 16);
                aL[half*2 + 0] = (uint32_t)l0s | ((uint32_t)l1s << 16);
                aL[half*2 + 1] = (uint32_t)l2s | ((uint32_t)l3s << 16);
            }
            // fix interleave: aH = {t2ks.e01, t2ks.e23, t2ks1.e01, t2ks1.e23}
            // (half=0 wrote slots 0,1; half=1 wrote slots 2,3 — correct)
            uint32_t vh4[4][4], vl4[4][4];
            #pragma unroll
            for (int p = 0; p < 4; p++) {
                uint32_t vo = (uint32_t)((ks >> 1) * 4096) +
                              tile_off(p*16 + (g >> 1)*8 + l8, 2*(ks & 1) + (g & 1));
                ldsm4(vh4[p], sb + AT_VH + vo);
                ldsm4(vl4[p], sb + AT_VL + vo);
            }
            #pragma unroll
            for (int nt = 0; nt < 8; nt++) {
                const uint32_t* bhv = &vh4[nt >> 1][(nt & 1) * 2];
                const uint32_t* blv = &vl4[nt >> 1][(nt & 1) * 2];
                mma_bf16(acc[nt], aH, bhv);
                mma_bf16(acc[nt], aL, bhv);
                mma_bf16(acc[nt], aH, blv);
            }
        }

        __syncthreads();
        if (it + 2 < NT) load_kv((it + 2) * 64, it & 1);
    }

    // ---- epilogue: normalize, split to bf16 hi/lo, write [B,S,D] ----
    float i0 = 1.f / l0, i1 = 1.f / l1;
    int b = bh >> 4, h = bh & 15;
    int s0r = q0 + warp * 16 + rl;
    #pragma unroll
    for (int nt = 0; nt < 8; nt++) {
        int col = h * 64 + nt * 8 + cl;
        {
            float w0 = acc[nt][0] * i0, w1 = acc[nt][1] * i0;
            unsigned short h0,lo0,h1,lo1;
            split1(w0, h0, lo0); split1(w1, h1, lo1);
            size_t ob = (size_t)(b * SS + s0r) * DD + col;
            reinterpret_cast<uint32_t*>(Oh)[ob >> 1] = (uint32_t)h0  | ((uint32_t)h1  << 16);
            reinterpret_cast<uint32_t*>(Ol)[ob >> 1] = (uint32_t)lo0 | ((uint32_t)lo1 << 16);
        }
        {
            float w0 = acc[nt][2] * i1, w1 = acc[nt][3] * i1;
            unsigned short h0,lo0,h1,lo1;
            split1(w0, h0, lo0); split1(w1, h1, lo1);
            size_t ob = (size_t)(b * SS + s0r + 8) * DD + col;
            reinterpret_cast<uint32_t*>(Oh)[ob >> 1] = (uint32_t)h0  | ((uint32_t)h1  << 16);
            reinterpret_cast<uint32_t*>(Ol)[ob >> 1] = (uint32_t)lo0 | ((uint32_t)lo1 << 16);
        }
    }
}

// ---------------- host launch ----------------
extern "C" void kernel_launch(void* const* d_in, const int* in_sizes, int n_in,
                              void* d_out, int out_size)
{
    const float* x     = (const float*)d_in[0];
    const float* Wq    = (const float*)d_in[1];
    const float* bq    = (const float*)d_in[2];
    const float* Wk    = (const float*)d_in[3];
    const float* bk    = (const float*)d_in[4];
    const float* Wv    = (const float*)d_in[5];
    const float* bv    = (const float*)d_in[6];
    const float* Wo    = (const float*)d_in[7];
    const float* bo    = (const float*)d_in[8];
    const float* W1    = (const float*)d_in[9];
    const float* b1    = (const float*)d_in[10];
    const float* W2    = (const float*)d_in[11];
    const float* b2    = (const float*)d_in[12];
    const float* g1    = (const float*)d_in[13];
    const float* beta1 = (const float*)d_in[14];
    const float* g2    = (const float*)d_in[15];
    const float* beta2 = (const float*)d_in[16];
    float* out = (float*)d_out;

    float *qkv, *x1, *bqkv;
    __nv_bfloat16 *xnh, *xnl, *xn2h, *xn2l, *ath, *atl, *hh, *hl;
    __nv_bfloat16 *qh, *ql, *kh, *kl, *vth, *vtl;
    __nv_bfloat16 *qkvth, *qkvtl, *woth, *wotl, *w1th, *w1tl, *w2th, *w2tl;
    cudaGetSymbolAddress((void**)&qkv,   g_qkv);
    cudaGetSymbolAddress((void**)&x1,    g_x1);
    cudaGetSymbolAddress((void**)&bqkv,  g_bqkv);
    cudaGetSymbolAddress((void**)&xnh,   g_xn_h);
    cudaGetSymbolAddress((void**)&xnl,   g_xn_l);
    cudaGetSymbolAddress((void**)&xn2h,  g_xn2_h);
    cudaGetSymbolAddress((void**)&xn2l,  g_xn2_l);
    cudaGetSymbolAddress((void**)&ath,   g_at_h);
    cudaGetSymbolAddress((void**)&atl,   g_at_l);
    cudaGetSymbolAddress((void**)&hh,    g_h_h);
    cudaGetSymbolAddress((void**)&hl,    g_h_l);
    cudaGetSymbolAddress((void**)&qh,    g_q_h);
    cudaGetSymbolAddress((void**)&ql,    g_q_l);
    cudaGetSymbolAddress((void**)&kh,    g_k_h);
    cudaGetSymbolAddress((void**)&kl,    g_k_l);
    cudaGetSymbolAddress((void**)&vth,   g_vt_h);
    cudaGetSymbolAddress((void**)&vtl,   g_vt_l);
    cudaGetSymbolAddress((void**)&qkvth, g_qkvt_h);
    cudaGetSymbolAddress((void**)&qkvtl, g_qkvt_l);
    cudaGetSymbolAddress((void**)&woth,  g_wot_h);
    cudaGetSymbolAddress((void**)&wotl,  g_wot_l);
    cudaGetSymbolAddress((void**)&w1th,  g_w1t_h);
    cudaGetSymbolAddress((void**)&w1tl,  g_w1t_l);
    cudaGetSymbolAddress((void**)&w2th,  g_w2t_h);
    cudaGetSymbolAddress((void**)&w2tl,  g_w2t_l);

    cudaFuncSetAttribute(gemm_mma, cudaFuncAttributeMaxDynamicSharedMemorySize, MSMEM);
    cudaFuncSetAttribute(attn_mma, cudaFuncAttributeMaxDynamicSharedMemorySize, ATTN_SMEM);

    // weight prep: transpose + hi/lo split
    wsplit_t<<<dim3(DD/32, DD/32), 256>>>(Wq, qkvth,            qkvtl,            DD, DD);
    wsplit_t<<<dim3(DD/32, DD/32), 256>>>(Wk, qkvth + DD*DD,    qkvtl + DD*DD,    DD, DD);
    wsplit_t<<<dim3(DD/32, DD/32), 256>>>(Wv, qkvth + 2*DD*DD,  qkvtl + 2*DD*DD,  DD, DD);
    wsplit_t<<<dim3(DD/32, DD/32), 256>>>(Wo, woth, wotl, DD, DD);
    wsplit_t<<<dim3(FF/32, DD/32), 256>>>(W1, w1th, w1tl, DD, FF);
    wsplit_t<<<dim3(DD/32, FF/32), 256>>>(W2, w2th, w2tl, FF, DD);
    bias3<<<3*DD/256, 256>>>(bq, bk, bv, bqkv);

    // LN1 -> split
    ln_split<<<NN, 256>>>(x, g1, beta1, xnh, xnl);

    // fused QKV projection (N=3072), scatter epilogue -> fp32 q,k,v
    gemm_mma<<<dim3(3*DD/128, NN/128), 256, MSMEM>>>(
        xnh, xnl, qkvth, qkvtl, bqkv, nullptr, qkv, nullptr, nullptr,
        NN, DD, 3*DD, MODE_QKV3);

    float* q = qkv;
    float* k = qkv + (size_t)NN*DD;
    float* v = qkv + 2*(size_t)NN*DD;

    // RoPE + split to bf16 hi/lo
    int ropeBlocks = (BB*HH*SS*(HD/2)) / 256;
    rope_split<<<ropeBlocks, 256>>>(q, qh, ql, 0.125f);
    rope_split<<<ropeBlocks, 256>>>(k, kh, kl, 1.0f);
    // V transpose + split
    vsplit_t<<<dim3(SS/32, HD/32, BB*HH), 256>>>(v, vth, vtl);

    // MMA flash attention -> bf16 hi/lo attn output [B,S,D]
    attn_mma<<<dim3(SS/128, BB*HH), 256, ATTN_SMEM>>>(qh, ql, kh, kl, vth, vtl, ath, atl);

    // x1 = x + attn @ Wo + bo
    gemm_mma<<<dim3(DD/128, NN/128), 256, MSMEM>>>(
        ath, atl, woth, wotl, bo, x, x1, nullptr, nullptr,
        NN, DD, DD, MODE_RESID);

    // LN2 -> split
    ln_split<<<NN, 256>>>(x1, g2, beta2, xn2h, xn2l);

    // FFN up: relu + split epilogue
    gemm_mma<<<dim3(FF/128, NN/128), 256, MSMEM>>>(
        xn2h, xn2l, w1th, w1tl, b1, nullptr, nullptr, hh, hl,
        NN, DD, FF, MODE_RELU_SPLIT);

    // FFN down + residual -> out
    gemm_mma<<<dim3(DD/128, NN/128), 256, MSMEM>>>(
        hh, hl, w2th, w2tl, b2, x1, out, nullptr, nullptr,
        NN, FF, DD, MODE_RESID);
}

// round 7
// speedup vs baseline: 3.0071x; 1.0358x over previous
#include <cuda_runtime.h>
#include <cuda_bf16.h>
#include <math.h>
#include <stdint.h>

#define BB 2
#define SS 2048
#define DD 1024
#define HH 16
#define HD 64
#define FF 4096
#define NN (BB*SS)   // 4096 tokens

// ---------------- scratch (static device globals; no allocs) ----------------
__device__ float g_x1  [NN*DD];      // x + attn_out
__device__ __nv_bfloat16 g_xn_h [NN*DD], g_xn_l [NN*DD];
__device__ __nv_bfloat16 g_xn2_h[NN*DD], g_xn2_l[NN*DD];
__device__ __nv_bfloat16 g_at_h [NN*DD], g_at_l [NN*DD];   // attn out [B,S,D]
__device__ __nv_bfloat16 g_qkvb_h[3u*NN*DD], g_qkvb_l[3u*NN*DD]; // q,k,v [t][B,H,S,hd]
__device__ __nv_bfloat16 g_h_h  [(size_t)NN*FF], g_h_l[(size_t)NN*FF];
__device__ __nv_bfloat16 g_qkvt_h[3*DD*DD], g_qkvt_l[3*DD*DD]; // [3072,1024]
__device__ __nv_bfloat16 g_wot_h [DD*DD],   g_wot_l [DD*DD];
__device__ __nv_bfloat16 g_w1t_h [FF*DD],   g_w1t_l [FF*DD];
__device__ __nv_bfloat16 g_w2t_h [DD*FF],   g_w2t_l [DD*FF];
__device__ float g_bqkv[3*DD];

// ---------------- helpers ----------------
__device__ __forceinline__ uint32_t smem_u32(const void* p) {
    return (uint32_t)__cvta_generic_to_shared(p);
}
__device__ __forceinline__ void cp16(uint32_t s, const void* g) {
    asm volatile("cp.async.cg.shared.global [%0], [%1], 16;" :: "r"(s), "l"(g));
}
__device__ __forceinline__ void cp_commit() {
    asm volatile("cp.async.commit_group;" ::: "memory");
}
__device__ __forceinline__ void ldsm4(uint32_t* r, uint32_t addr) {
    asm volatile("ldmatrix.sync.aligned.m8n8.x4.shared.b16 {%0,%1,%2,%3}, [%4];"
        : "=r"(r[0]), "=r"(r[1]), "=r"(r[2]), "=r"(r[3]) : "r"(addr));
}
__device__ __forceinline__ void ldsm4t(uint32_t* r, uint32_t addr) {
    asm volatile("ldmatrix.sync.aligned.m8n8.x4.trans.shared.b16 {%0,%1,%2,%3}, [%4];"
        : "=r"(r[0]), "=r"(r[1]), "=r"(r[2]), "=r"(r[3]) : "r"(addr));
}
__device__ __forceinline__ void mma_bf16(float* d, const uint32_t* a, const uint32_t* b) {
    asm volatile("mma.sync.aligned.m16n8k16.row.col.f32.bf16.bf16.f32 "
        "{%0,%1,%2,%3}, {%4,%5,%6,%7}, {%8,%9}, {%0,%1,%2,%3};"
        : "+f"(d[0]), "+f"(d[1]), "+f"(d[2]), "+f"(d[3])
        : "r"(a[0]), "r"(a[1]), "r"(a[2]), "r"(a[3]), "r"(b[0]), "r"(b[1]));
}
__device__ __forceinline__ void split1(float x, unsigned short& h, unsigned short& l) {
    __nv_bfloat16 hb = __float2bfloat16(x);
    float hf = __bfloat162float(hb);
    __nv_bfloat16 lb = __float2bfloat16(x - hf);
    h = __bfloat16_as_ushort(hb);
    l = __bfloat16_as_ushort(lb);
}
// swizzled offset inside a 64B-wide tile: (row, 16B-chunk c in 0..3)
__device__ __forceinline__ uint32_t tile_off(int r, int c) {
    return (uint32_t)(((r >> 1) * 128) + (((((r & 1) << 2) | c) ^ ((r >> 1) & 7)) << 4));
}

// ---------------- LayerNorm with bf16 hi/lo split output ----------------
__global__ __launch_bounds__(256) void ln_split(const float* __restrict__ x,
                                                const float* __restrict__ gamma,
                                                const float* __restrict__ beta,
                                                __nv_bfloat16* __restrict__ oh,
                                                __nv_bfloat16* __restrict__ ol)
{
    int row = blockIdx.x;
    const float4* xr = reinterpret_cast<const float4*>(x + (size_t)row * DD);
    float4 v = xr[threadIdx.x];

    float s  = v.x + v.y + v.z + v.w;
    float sq = v.x*v.x + v.y*v.y + v.z*v.z + v.w*v.w;
    #pragma unroll
    for (int o = 16; o > 0; o >>= 1) {
        s  += __shfl_xor_sync(0xffffffffu, s,  o);
        sq += __shfl_xor_sync(0xffffffffu, sq, o);
    }
    __shared__ float ps[8], psq[8];
    int wid = threadIdx.x >> 5, lane = threadIdx.x & 31;
    if (lane == 0) { ps[wid] = s; psq[wid] = sq; }
    __syncthreads();
    float ts = 0.f, tsq = 0.f;
    #pragma unroll
    for (int i = 0; i < 8; i++) { ts += ps[i]; tsq += psq[i]; }

    float mu   = ts * (1.0f / DD);
    float var  = tsq * (1.0f / DD) - mu * mu;
    float rstd = rsqrtf(var + 1e-5f);

    float4 g = reinterpret_cast<const float4*>(gamma)[threadIdx.x];
    float4 b = reinterpret_cast<const float4*>(beta )[threadIdx.x];
    float o0 = (v.x - mu) * rstd * g.x + b.x;
    float o1 = (v.y - mu) * rstd * g.y + b.y;
    float o2 = (v.z - mu) * rstd * g.z + b.z;
    float o3 = (v.w - mu) * rstd * g.w + b.w;

    unsigned short h0,h1,h2,h3, l0,l1,l2,l3;
    split1(o0,h0,l0); split1(o1,h1,l1); split1(o2,h2,l2); split1(o3,h3,l3);
    uint2 hv = make_uint2((uint32_t)h0 | ((uint32_t)h1<<16), (uint32_t)h2 | ((uint32_t)h3<<16));
    uint2 lv = make_uint2((uint32_t)l0 | ((uint32_t)l1<<16), (uint32_t)l2 | ((uint32_t)l3<<16));
    reinterpret_cast<uint2*>(oh + (size_t)row*DD)[threadIdx.x] = hv;
    reinterpret_cast<uint2*>(ol + (size_t)row*DD)[threadIdx.x] = lv;
}

// ---------------- all-weights transpose + split (single launch) ----------------
__global__ __launch_bounds__(256) void wsplit_all(
    const float* __restrict__ Wq, const float* __restrict__ Wk,
    const float* __restrict__ Wv, const float* __restrict__ Wo,
    const float* __restrict__ W1, const float* __restrict__ W2,
    __nv_bfloat16* __restrict__ qkvth, __nv_bfloat16* __restrict__ qkvtl,
    __nv_bfloat16* __restrict__ woth,  __nv_bfloat16* __restrict__ wotl,
    __nv_bfloat16* __restrict__ w1th,  __nv_bfloat16* __restrict__ w1tl,
    __nv_bfloat16* __restrict__ w2th,  __nv_bfloat16* __restrict__ w2tl)
{
    int z = blockIdx.z;
    const float* W;
    __nv_bfloat16 *Bh, *Bl;
    int K, N, n0, k0;
    if (z < 4) {
        W  = (z==0) ? Wq : (z==1) ? Wk : (z==2) ? Wv : Wo;
        Bh = (z<3) ? qkvth + (size_t)z*DD*DD : woth;
        Bl = (z<3) ? qkvtl + (size_t)z*DD*DD : wotl;
        K = DD; N = DD;
        n0 = blockIdx.x * 32; k0 = blockIdx.y * 32;
    } else if (z < 8) {
        W = W1; Bh = w1th; Bl = w1tl; K = DD; N = FF;
        n0 = (z-4)*1024 + blockIdx.x * 32; k0 = blockIdx.y * 32;
    } else {
        W = W2; Bh = w2th; Bl = w2tl; K = FF; N = DD;
        n0 = blockIdx.x * 32; k0 = (z-8)*1024 + blockIdx.y * 32;
    }

    __shared__ float t[32][33];
    int tx = threadIdx.x & 31, ty = threadIdx.x >> 5;
    #pragma unroll
    for (int r = 0; r < 4; r++)
        t[ty + 8*r][tx] = W[(size_t)(k0 + ty + 8*r) * N + n0 + tx];
    __syncthreads();
    #pragma unroll
    for (int r = 0; r < 4; r++) {
        int n = ty + 8*r, k = tx;
        float x = t[k][n];
        unsigned short h, l;
        split1(x, h, l);
        size_t o = (size_t)(n0 + n) * K + k0 + k;
        Bh[o] = __ushort_as_bfloat16(h);
        Bl[o] = __ushort_as_bfloat16(l);
    }
}

// ---------------- concat q/k/v biases ----------------
__global__ void bias3(const float* a, const float* b, const float* c, float* o) {
    int i = blockIdx.x * 256 + threadIdx.x;
    o[i] = (i < DD) ? a[i] : (i < 2*DD) ? b[i - DD] : c[i - 2*DD];
}

// ---------------- split-bf16 warp-MMA GEMM: BK=64, 3-stage pipeline ----------------
#define MBK 64
#define SOFF_AHI 0
#define SOFF_ALO 16384
#define SOFF_BHI 32768
#define SOFF_BLO 49152
#define MSTAGE 65536
#define MSMEM (3*MSTAGE)

#define MODE_QKV3       1
#define MODE_RESID      2
#define MODE_RELU_SPLIT 3

__global__ __launch_bounds__(256, 1) void gemm_mma(
    const __nv_bfloat16* __restrict__ Ah, const __nv_bfloat16* __restrict__ Al,
    const __nv_bfloat16* __restrict__ Bh, const __nv_bfloat16* __restrict__ Bl,
    const float* __restrict__ bias, const float* __restrict__ resid,
    float* __restrict__ Cf, __nv_bfloat16* __restrict__ Ch, __nv_bfloat16* __restrict__ Cl,
    int M, int K, int N, int mode)
{
    extern __shared__ char smraw[];
    const uint32_t smbase = smem_u32(smraw);

    const int tid  = threadIdx.x;
    const int warp = tid >> 5;
    const int lane = tid & 31;
    const int warpMoff = (warp & 1) * 64;
    const int warpNoff = (warp >> 1) * 32;
    const int mBase = blockIdx.y * 128;
    const int nBase = blockIdx.x * 128;
    const int nk = K / MBK;

    const int g = lane >> 3, l8 = lane & 7;
    uint32_t aoff[4][4], boff[4][2];
    #pragma unroll
    for (int ks = 0; ks < 4; ks++) {
        #pragma unroll
        for (int mt = 0; mt < 4; mt++)
            aoff[ks][mt] = (uint32_t)((ks >> 1) * 8192) +
                           tile_off(warpMoff + mt*16 + (g & 1)*8 + l8, 2*(ks & 1) + (g >> 1));
        #pragma unroll
        for (int p = 0; p < 2; p++)
            boff[ks][p]  = (uint32_t)((ks >> 1) * 8192) +
                           tile_off(warpNoff + p*16 + (g >> 1)*8 + l8, 2*(ks & 1) + (g & 1));
    }

    auto load_stage = [&](int chunk, int s) {
        const int k0 = chunk * MBK;
        uint32_t sb = smbase + (uint32_t)s * MSTAGE;
        #pragma unroll
        for (int h = 0; h < 4; h++) {
            int id = tid + h * 256;
            int r = id >> 3, c = id & 7;
            uint32_t so = (uint32_t)((c >> 2) * 8192) + tile_off(r, c & 3);
            size_t ga = ((size_t)(mBase + r) * K + k0 + c*8) * 2;
            size_t gb = ((size_t)(nBase + r) * K + k0 + c*8) * 2;
            cp16(sb + SOFF_AHI + so, (const char*)Ah + ga);
            cp16(sb + SOFF_ALO + so, (const char*)Al + ga);
            cp16(sb + SOFF_BHI + so, (const char*)Bh + gb);
            cp16(sb + SOFF_BLO + so, (const char*)Bl + gb);
        }
        cp_commit();
    };

    load_stage(0, 0);
    load_stage(1, 1);
    load_stage(2, 2);

    float acc[4][4][4];
    #pragma unroll
    for (int mt = 0; mt < 4; mt++)
        #pragma unroll
        for (int nt = 0; nt < 4; nt++)
            #pragma unroll
            for (int e = 0; e < 4; e++) acc[mt][nt][e] = 0.f;

    for (int chunk = 0; chunk < nk; chunk++) {
        const int s = chunk % 3;
        const int rem = nk - 1 - chunk;
        if (rem >= 2)      asm volatile("cp.async.wait_group 2;" ::: "memory");
        else if (rem == 1) asm volatile("cp.async.wait_group 1;" ::: "memory");
        else               asm volatile("cp.async.wait_group 0;" ::: "memory");
        __syncthreads();

        const uint32_t sb = smbase + (uint32_t)s * MSTAGE;
        #pragma unroll
        for (int ks = 0; ks < 4; ks++) {
            uint32_t ahi[4][4], alo[4][4], bhi[4][2], blo[4][2];
            #pragma unroll
            for (int mt = 0; mt < 4; mt++) {
                ldsm4(ahi[mt], sb + SOFF_AHI + aoff[ks][mt]);
                ldsm4(alo[mt], sb + SOFF_ALO + aoff[ks][mt]);
            }
            #pragma unroll
            for (int p = 0; p < 2; p++) {
                ldsm4(&bhi[2*p][0], sb + SOFF_BHI + boff[ks][p]);
                ldsm4(&blo[2*p][0], sb + SOFF_BLO + boff[ks][p]);
            }
            #pragma unroll
            for (int nt = 0; nt < 4; nt++)
                #pragma unroll
                for (int mt = 0; mt < 4; mt++) {
                    mma_bf16(acc[mt][nt], ahi[mt], bhi[nt]);
                    mma_bf16(acc[mt][nt], ahi[mt], blo[nt]);
                    mma_bf16(acc[mt][nt], alo[mt], bhi[nt]);
                }
        }
        __syncthreads();
        if (chunk + 3 < nk) load_stage(chunk + 3, s);
    }

    // ---------------- epilogue ----------------
    const int rl = lane >> 2;
    const int cl = (lane & 3) * 2;

    #pragma unroll
    for (int mt = 0; mt < 4; mt++) {
        #pragma unroll
        for (int nt = 0; nt < 4; nt++) {
            int gr0 = mBase + warpMoff + mt*16 + rl;
            int gc  = nBase + warpNoff + nt*8 + cl;
            float b0 = __ldg(&bias[gc]);
            float b1 = __ldg(&bias[gc + 1]);
            float v00 = acc[mt][nt][0] + b0, v01 = acc[mt][nt][1] + b1;
            float v10 = acc[mt][nt][2] + b0, v11 = acc[mt][nt][3] + b1;

            if (mode == MODE_QKV3) {
                int t = gc >> 10;
                int within = gc & 1023;
                int h = within >> 6, jj = within & 63;
                int p = jj >> 1;
                float inv = expf(-0.28782313663f * (float)p);   // 10000^(-p/32)
                #pragma unroll
                for (int rr = 0; rr < 2; rr++) {
                    int row = gr0 + rr*8;
                    int b = row >> 11, sI = row & 2047;
                    float w0 = rr ? v10 : v00;
                    float w1 = rr ? v11 : v01;
                    if (t < 2) {
                        float sn, cs;
                        sincosf((float)sI * inv, &sn, &cs);
                        float r0 = w0 * cs - w1 * sn;
                        float r1 = w0 * sn + w1 * cs;
                        if (t == 0) { r0 *= 0.125f; r1 *= 0.125f; }
                        w0 = r0; w1 = r1;
                    }
                    unsigned short h0,l0,h1,l1;
                    split1(w0, h0, l0);
                    split1(w1, h1, l1);
                    size_t ob = (size_t)t * NN * DD +
                                ((size_t)((b*HH + h)*SS + sI)) * HD + jj;
                    reinterpret_cast<uint32_t*>(Ch)[ob >> 1] = (uint32_t)h0 | ((uint32_t)h1 << 16);
                    reinterpret_cast<uint32_t*>(Cl)[ob >> 1] = (uint32_t)l0 | ((uint32_t)l1 << 16);
                }
            } else if (mode == MODE_RESID) {
                #pragma unroll
                for (int rr = 0; rr < 2; rr++) {
                    int row = gr0 + rr*8;
                    size_t ob = (size_t)row * N + gc;
                    float2 rv = *reinterpret_cast<const float2*>(resid + ob);
                    float2 o = rr ? make_float2(v10 + rv.x, v11 + rv.y)
                                  : make_float2(v00 + rv.x, v01 + rv.y);
                    *reinterpret_cast<float2*>(Cf + ob) = o;
                }
            } else { // MODE_RELU_SPLIT
                #pragma unroll
                for (int rr = 0; rr < 2; rr++) {
                    int row = gr0 + rr*8;
                    size_t ob = (size_t)row * N + gc;
                    float w0 = fmaxf(rr ? v10 : v00, 0.f);
                    float w1 = fmaxf(rr ? v11 : v01, 0.f);
                    unsigned short h0,l0,h1,l1;
                    split1(w0, h0, l0);
                    split1(w1, h1, l1);
                    reinterpret_cast<uint32_t*>(Ch)[ob >> 1] = (uint32_t)h0 | ((uint32_t)h1 << 16);
                    reinterpret_cast<uint32_t*>(Cl)[ob >> 1] = (uint32_t)l0 | ((uint32_t)l1 << 16);
                }
            }
        }
    }
}

// ---------------- split-bf16 MMA flash attention (V row-major + ldmatrix.trans) ----------------
#define AT_SQH   0
#define AT_SQL   16384
#define AT_STAGE 32768
#define AT_SSZ   32768
#define AT_KH    0
#define AT_KL    8192
#define AT_VH    16384
#define AT_VL    24576
#define ATTN_SMEM (32768 + 2*32768)

__global__ __launch_bounds__(256, 2) void attn_mma(
    const __nv_bfloat16* __restrict__ Qh, const __nv_bfloat16* __restrict__ Ql,
    const __nv_bfloat16* __restrict__ Kh, const __nv_bfloat16* __restrict__ Kl,
    const __nv_bfloat16* __restrict__ Vh, const __nv_bfloat16* __restrict__ Vl,
    __nv_bfloat16* __restrict__ Oh, __nv_bfloat16* __restrict__ Ol)
{
    extern __shared__ char smraw[];
    const uint32_t sm = smem_u32(smraw);
    const int tid = threadIdx.x, warp = tid >> 5, lane = tid & 31;
    const int bh = blockIdx.y;
    const int q0 = blockIdx.x * 128;
    const int g = lane >> 3, l8 = lane & 7;
    const int rl = lane >> 2, cl = (lane & 3) * 2;

    // load Q tiles (hi/lo), part of first commit group
    #pragma unroll
    for (int t = 0; t < 8; t++) {
        int buf = t >> 2;                    // 0=hi,1=lo
        int w = (t & 3) * 256 + tid;         // 0..1023
        int r = w >> 3, c = w & 7;
        uint32_t off = (buf ? AT_SQL : AT_SQH) + (c >> 2) * 8192 + tile_off(r, c & 3);
        const char* gp = (const char*)(buf ? Ql : Qh) +
                         ((size_t)((size_t)bh * SS + q0 + r) * HD + c * 8) * 2;
        cp16(sm + off, gp);
    }

    auto load_kv = [&](int kb, int s) {
        uint32_t sb = sm + AT_STAGE + (uint32_t)s * AT_SSZ;
        #pragma unroll
        for (int t = 0; t < 8; t++) {
            int buf = t >> 1;                // 0=Kh 1=Kl 2=Vh 3=Vl
            int w = (t & 1) * 256 + tid;     // 0..511
            int r = w >> 3, c = w & 7;
            uint32_t off = (uint32_t)buf * 8192 + (c >> 2) * 4096 + tile_off(r, c & 3);
            const __nv_bfloat16* src = (buf == 0) ? Kh : (buf == 1) ? Kl : (buf == 2) ? Vh : Vl;
            const char* gp = (const char*)src + ((size_t)((size_t)bh * SS + kb + r) * HD + c * 8) * 2;
            cp16(sb + off, gp);
        }
        cp_commit();
    };

    load_kv(0, 0);
    load_kv(64, 1);

    float m0 = -1e30f, m1 = -1e30f, l0 = 0.f, l1 = 0.f;
    float acc[8][4];
    #pragma unroll
    for (int nt = 0; nt < 8; nt++)
        #pragma unroll
        for (int e = 0; e < 4; e++) acc[nt][e] = 0.f;

    const int NT = SS / 64;
    for (int it = 0; it < NT; it++) {
        if (it + 1 < NT) asm volatile("cp.async.wait_group 1;" ::: "memory");
        else             asm volatile("cp.async.wait_group 0;" ::: "memory");
        __syncthreads();
        const uint32_t sb = sm + AT_STAGE + (uint32_t)(it & 1) * AT_SSZ;

        // ---- S = Q K^T (split 3-product) ----
        float sacc[8][4];
        #pragma unroll
        for (int nt = 0; nt < 8; nt++)
            #pragma unroll
            for (int e = 0; e < 4; e++) sacc[nt][e] = 0.f;

        #pragma unroll
        for (int ks = 0; ks < 4; ks++) {
            uint32_t qoff = (uint32_t)((ks >> 1) * 8192) +
                            tile_off(warp*16 + (g & 1)*8 + l8, 2*(ks & 1) + (g >> 1));
            uint32_t qh4[4], ql4[4];
            ldsm4(qh4, sm + AT_SQH + qoff);
            ldsm4(ql4, sm + AT_SQL + qoff);
            uint32_t kh4[4][4], kl4[4][4];
            #pragma unroll
            for (int p = 0; p < 4; p++) {
                uint32_t ko = (uint32_t)((ks >> 1) * 4096) +
                              tile_off(p*16 + (g >> 1)*8 + l8, 2*(ks & 1) + (g & 1));
                ldsm4(kh4[p], sb + AT_KH + ko);
                ldsm4(kl4[p], sb + AT_KL + ko);
            }
            #pragma unroll
            for (int nt = 0; nt < 8; nt++) {
                const uint32_t* bhk = &kh4[nt >> 1][(nt & 1) * 2];
                const uint32_t* blk = &kl4[nt >> 1][(nt & 1) * 2];
                mma_bf16(sacc[nt], qh4, bhk);
                mma_bf16(sacc[nt], qh4, blk);
                mma_bf16(sacc[nt], ql4, bhk);
            }
        }

        // ---- online softmax ----
        float mx0 = -1e30f, mx1 = -1e30f;
        #pragma unroll
        for (int nt = 0; nt < 8; nt++) {
            mx0 = fmaxf(mx0, fmaxf(sacc[nt][0], sacc[nt][1]));
            mx1 = fmaxf(mx1, fmaxf(sacc[nt][2], sacc[nt][3]));
        }
        mx0 = fmaxf(mx0, __shfl_xor_sync(0xffffffffu, mx0, 1));
        mx0 = fmaxf(mx0, __shfl_xor_sync(0xffffffffu, mx0, 2));
        mx1 = fmaxf(mx1, __shfl_xor_sync(0xffffffffu, mx1, 1));
        mx1 = fmaxf(mx1, __shfl_xor_sync(0xffffffffu, mx1, 2));

        float mn0 = fmaxf(m0, mx0), mn1 = fmaxf(m1, mx1);
        float a0 = __expf(m0 - mn0), a1 = __expf(m1 - mn1);
        float rs0 = 0.f, rs1 = 0.f;
        #pragma unroll
        for (int nt = 0; nt < 8; nt++) {
            sacc[nt][0] = __expf(sacc[nt][0] - mn0);
            sacc[nt][1] = __expf(sacc[nt][1] - mn0);
            sacc[nt][2] = __expf(sacc[nt][2] - mn1);
            sacc[nt][3] = __expf(sacc[nt][3] - mn1);
            rs0 += sacc[nt][0] + sacc[nt][1];
            rs1 += sacc[nt][2] + sacc[nt][3];
        }
        rs0 += __shfl_xor_sync(0xffffffffu, rs0, 1);
        rs0 += __shfl_xor_sync(0xffffffffu, rs0, 2);
        rs1 += __shfl_xor_sync(0xffffffffu, rs1, 1);
        rs1 += __shfl_xor_sync(0xffffffffu, rs1, 2);
        l0 = l0 * a0 + rs0;  m0 = mn0;
        l1 = l1 * a1 + rs1;  m1 = mn1;
        #pragma unroll
        for (int nt = 0; nt < 8; nt++) {
            acc[nt][0] *= a0; acc[nt][1] *= a0;
            acc[nt][2] *= a1; acc[nt][3] *= a1;
        }

        // ---- O += P V (split 3-product); V row-major, trans ldmatrix ----
        #pragma unroll
        for (int ks = 0; ks < 4; ks++) {
            uint32_t aH[4], aL[4];
            #pragma unroll
            for (int half = 0; half < 2; half++) {
                int nt = 2*ks + half;
                unsigned short h0,l0s,h1,l1s,h2,l2s,h3,l3s;
                split1(sacc[nt][0], h0, l0s);
                split1(sacc[nt][1], h1, l1s);
                split1(sacc[nt][2], h2, l2s);
                split1(sacc[nt][3], h3, l3s);
                aH[half*2 + 0] = (uint32_t)h0  | ((uint32_t)h1  << 16);
                aH[half*2 + 1] = (uint32_t)h2  | ((uint32_t)h3  << 16);
                aL[half*2 + 0] = (uint32_t)l0s | ((uint32_t)l1s << 16);
                aL[half*2 + 1] = (uint32_t)l2s | ((uint32_t)l3s << 16);
            }
            // V fragments via trans ldmatrix: per n-group p (d=16p..16p+15),
            // address = V row (key) 16*ks + (g&1)*8 + l8, d-chunk = p*2 + (g>>1)
            uint32_t vh4[4][4], vl4[4][4];
            int vrow = 16*ks + (g & 1)*8 + l8;
            #pragma unroll
            for (int p = 0; p < 4; p++) {
                int c = p*2 + (g >> 1);            // 16B d-chunk 0..7
                uint32_t vo = (uint32_t)((c >> 2) * 4096) + tile_off(vrow, c & 3);
                ldsm4t(vh4[p], sb + AT_VH + vo);
                ldsm4t(vl4[p], sb + AT_VL + vo);
            }
            #pragma unroll
            for (int nt = 0; nt < 8; nt++) {
                const uint32_t* bhv = &vh4[nt >> 1][(nt & 1) * 2];
                const uint32_t* blv = &vl4[nt >> 1][(nt & 1) * 2];
                mma_bf16(acc[nt], aH, bhv);
                mma_bf16(acc[nt], aL, bhv);
                mma_bf16(acc[nt], aH, blv);
            }
        }

        __syncthreads();
        if (it + 2 < NT) load_kv((it + 2) * 64, it & 1);
    }

    // ---- epilogue: normalize, split to bf16 hi/lo, write [B,S,D] ----
    float i0 = 1.f / l0, i1 = 1.f / l1;
    int b = bh >> 4, h = bh & 15;
    int s0r = q0 + warp * 16 + rl;
    #pragma unroll
    for (int nt = 0; nt < 8; nt++) {
        int col = h * 64 + nt * 8 + cl;
        {
            float w0 = acc[nt][0] * i0, w1 = acc[nt][1] * i0;
            unsigned short h0,lo0,h1,lo1;
            split1(w0, h0, lo0); split1(w1, h1, lo1);
            size_t ob = (size_t)(b * SS + s0r) * DD + col;
            reinterpret_cast<uint32_t*>(Oh)[ob >> 1] = (uint32_t)h0  | ((uint32_t)h1  << 16);
            reinterpret_cast<uint32_t*>(Ol)[ob >> 1] = (uint32_t)lo0 | ((uint32_t)lo1 << 16);
        }
        {
            float w0 = acc[nt][2] * i1, w1 = acc[nt][3] * i1;
            unsigned short h0,lo0,h1,lo1;
            split1(w0, h0, lo0); split1(w1, h1, lo1);
            size_t ob = (size_t)(b * SS + s0r + 8) * DD + col;
            reinterpret_cast<uint32_t*>(Oh)[ob >> 1] = (uint32_t)h0  | ((uint32_t)h1  << 16);
            reinterpret_cast<uint32_t*>(Ol)[ob >> 1] = (uint32_t)lo0 | ((uint32_t)lo1 << 16);
        }
    }
}

// ---------------- host launch ----------------
extern "C" void kernel_launch(void* const* d_in, const int* in_sizes, int n_in,
                              void* d_out, int out_size)
{
    const float* x     = (const float*)d_in[0];
    const float* Wq    = (const float*)d_in[1];
    const float* bq    = (const float*)d_in[2];
    const float* Wk    = (const float*)d_in[3];
    const float* bk    = (const float*)d_in[4];
    const float* Wv    = (const float*)d_in[5];
    const float* bv    = (const float*)d_in[6];
    const float* Wo    = (const float*)d_in[7];
    const float* bo    = (const float*)d_in[8];
    const float* W1    = (const float*)d_in[9];
    const float* b1    = (const float*)d_in[10];
    const float* W2    = (const float*)d_in[11];
    const float* b2    = (const float*)d_in[12];
    const float* g1    = (const float*)d_in[13];
    const float* beta1 = (const float*)d_in[14];
    const float* g2    = (const float*)d_in[15];
    const float* beta2 = (const float*)d_in[16];
    float* out = (float*)d_out;

    float *x1, *bqkv;
    __nv_bfloat16 *xnh, *xnl, *xn2h, *xn2l, *ath, *atl, *hh, *hl;
    __nv_bfloat16 *qkvbh, *qkvbl;
    __nv_bfloat16 *qkvth, *qkvtl, *woth, *wotl, *w1th, *w1tl, *w2th, *w2tl;
    cudaGetSymbolAddress((void**)&x1,    g_x1);
    cudaGetSymbolAddress((void**)&bqkv,  g_bqkv);
    cudaGetSymbolAddress((void**)&xnh,   g_xn_h);
    cudaGetSymbolAddress((void**)&xnl,   g_xn_l);
    cudaGetSymbolAddress((void**)&xn2h,  g_xn2_h);
    cudaGetSymbolAddress((void**)&xn2l,  g_xn2_l);
    cudaGetSymbolAddress((void**)&ath,   g_at_h);
    cudaGetSymbolAddress((void**)&atl,   g_at_l);
    cudaGetSymbolAddress((void**)&hh,    g_h_h);
    cudaGetSymbolAddress((void**)&hl,    g_h_l);
    cudaGetSymbolAddress((void**)&qkvbh, g_qkvb_h);
    cudaGetSymbolAddress((void**)&qkvbl, g_qkvb_l);
    cudaGetSymbolAddress((void**)&qkvth, g_qkvt_h);
    cudaGetSymbolAddress((void**)&qkvtl, g_qkvt_l);
    cudaGetSymbolAddress((void**)&woth,  g_wot_h);
    cudaGetSymbolAddress((void**)&wotl,  g_wot_l);
    cudaGetSymbolAddress((void**)&w1th,  g_w1t_h);
    cudaGetSymbolAddress((void**)&w1tl,  g_w1t_l);
    cudaGetSymbolAddress((void**)&w2th,  g_w2t_h);
    cudaGetSymbolAddress((void**)&w2tl,  g_w2t_l);

    cudaFuncSetAttribute(gemm_mma, cudaFuncAttributeMaxDynamicSharedMemorySize, MSMEM);
    cudaFuncSetAttribute(attn_mma, cudaFuncAttributeMaxDynamicSharedMemorySize, ATTN_SMEM);

    // 1: all weight transposes + splits in one launch
    wsplit_all<<<dim3(32, 32, 12), 256>>>(Wq, Wk, Wv, Wo, W1, W2,
                                          qkvth, qkvtl, woth, wotl,
                                          w1th, w1tl, w2th, w2tl);
    // 2
    bias3<<<3*DD/256, 256>>>(bq, bk, bv, bqkv);
    // 3: LN1 -> split
    ln_split<<<NN, 256>>>(x, g1, beta1, xnh, xnl);

    // 4: fused QKV projection + bias + RoPE + split (q,k,v bf16 hi/lo)
    gemm_mma<<<dim3(3*DD/128, NN/128), 256, MSMEM>>>(
        xnh, xnl, qkvth, qkvtl, bqkv, nullptr, nullptr, qkvbh, qkvbl,
        NN, DD, 3*DD, MODE_QKV3);

    __nv_bfloat16* qh = qkvbh;
    __nv_bfloat16* ql = qkvbl;
    __nv_bfloat16* kh = qkvbh + (size_t)NN*DD;
    __nv_bfloat16* kl = qkvbl + (size_t)NN*DD;
    __nv_bfloat16* vh = qkvbh + 2*(size_t)NN*DD;
    __nv_bfloat16* vl = qkvbl + 2*(size_t)NN*DD;

    // 5: MMA flash attention -> bf16 hi/lo attn output [B,S,D]
    attn_mma<<<dim3(SS/128, BB*HH), 256, ATTN_SMEM>>>(qh, ql, kh, kl, vh, vl, ath, atl);

    // 6: x1 = x + attn @ Wo + bo   (this is the ncu-profiled launch)
    gemm_mma<<<dim3(DD/128, NN/128), 256, MSMEM>>>(
        ath, atl, woth, wotl, bo, x, x1, nullptr, nullptr,
        NN, DD, DD, MODE_RESID);

    // 7: LN2 -> split
    ln_split<<<NN, 256>>>(x1, g2, beta2, xn2h, xn2l);

    // 8: FFN up: relu + split epilogue
    gemm_mma<<<dim3(FF/128, NN/128), 256, MSMEM>>>(
        xn2h, xn2l, w1th, w1tl, b1, nullptr, nullptr, hh, hl,
        NN, DD, FF, MODE_RELU_SPLIT);

    // 9: FFN down + residual -> out
    gemm_mma<<<dim3(DD/128, NN/128), 256, MSMEM>>>(
        hh, hl, w2th, w2tl, b2, x1, out, nullptr, nullptr,
        NN, FF, DD, MODE_RESID);
}

// round 8
// speedup vs baseline: 3.1961x; 1.0628x over previous
#include <cuda_runtime.h>
#include <cuda_bf16.h>
#include <math.h>
#include <stdint.h>

#define BB 2
#define SS 2048
#define DD 1024
#define HH 16
#define HD 64
#define FF 4096
#define NN (BB*SS)   // 4096 tokens

// ---------------- scratch (static device globals; no allocs) ----------------
__device__ float g_x1  [NN*DD];      // x + attn_out
__device__ __nv_bfloat16 g_xn_h [NN*DD], g_xn_l [NN*DD];
__device__ __nv_bfloat16 g_xn2_h[NN*DD], g_xn2_l[NN*DD];
__device__ __nv_bfloat16 g_at_h [NN*DD], g_at_l [NN*DD];   // attn out [B,S,D]
__device__ __nv_bfloat16 g_qkvb_h[3u*NN*DD], g_qkvb_l[3u*NN*DD]; // q,k,v [t][B,H,S,hd]
__device__ __nv_bfloat16 g_h_h  [(size_t)NN*FF], g_h_l[(size_t)NN*FF];
__device__ __nv_bfloat16 g_qkvt_h[3*DD*DD], g_qkvt_l[3*DD*DD]; // [3072,1024]
__device__ __nv_bfloat16 g_wot_h [DD*DD],   g_wot_l [DD*DD];
__device__ __nv_bfloat16 g_w1t_h [FF*DD],   g_w1t_l [FF*DD];
__device__ __nv_bfloat16 g_w2t_h [DD*FF],   g_w2t_l [DD*FF];
__device__ float g_bqkv[3*DD];

// ---------------- helpers ----------------
__device__ __forceinline__ uint32_t smem_u32(const void* p) {
    return (uint32_t)__cvta_generic_to_shared(p);
}
__device__ __forceinline__ void cp16(uint32_t s, const void* g) {
    asm volatile("cp.async.cg.shared.global [%0], [%1], 16;" :: "r"(s), "l"(g));
}
__device__ __forceinline__ void cp_commit() {
    asm volatile("cp.async.commit_group;" ::: "memory");
}
__device__ __forceinline__ void ldsm4(uint32_t* r, uint32_t addr) {
    asm volatile("ldmatrix.sync.aligned.m8n8.x4.shared.b16 {%0,%1,%2,%3}, [%4];"
        : "=r"(r[0]), "=r"(r[1]), "=r"(r[2]), "=r"(r[3]) : "r"(addr));
}
__device__ __forceinline__ void ldsm4t(uint32_t* r, uint32_t addr) {
    asm volatile("ldmatrix.sync.aligned.m8n8.x4.trans.shared.b16 {%0,%1,%2,%3}, [%4];"
        : "=r"(r[0]), "=r"(r[1]), "=r"(r[2]), "=r"(r[3]) : "r"(addr));
}
__device__ __forceinline__ void mma_bf16(float* d, const uint32_t* a, const uint32_t* b) {
    asm volatile("mma.sync.aligned.m16n8k16.row.col.f32.bf16.bf16.f32 "
        "{%0,%1,%2,%3}, {%4,%5,%6,%7}, {%8,%9}, {%0,%1,%2,%3};"
        : "+f"(d[0]), "+f"(d[1]), "+f"(d[2]), "+f"(d[3])
        : "r"(a[0]), "r"(a[1]), "r"(a[2]), "r"(a[3]), "r"(b[0]), "r"(b[1]));
}
__device__ __forceinline__ void split1(float x, unsigned short& h, unsigned short& l) {
    __nv_bfloat16 hb = __float2bfloat16(x);
    float hf = __bfloat162float(hb);
    __nv_bfloat16 lb = __float2bfloat16(x - hf);
    h = __bfloat16_as_ushort(hb);
    l = __bfloat16_as_ushort(lb);
}
// swizzled offset inside a 64B-wide tile: (row, 16B-chunk c in 0..3)
__device__ __forceinline__ uint32_t tile_off(int r, int c) {
    return (uint32_t)(((r >> 1) * 128) + (((((r & 1) << 2) | c) ^ ((r >> 1) & 7)) << 4));
}

// ---------------- LayerNorm with bf16 hi/lo split output ----------------
__global__ __launch_bounds__(256) void ln_split(const float* __restrict__ x,
                                                const float* __restrict__ gamma,
                                                const float* __restrict__ beta,
                                                __nv_bfloat16* __restrict__ oh,
                                                __nv_bfloat16* __restrict__ ol)
{
    int row = blockIdx.x;
    const float4* xr = reinterpret_cast<const float4*>(x + (size_t)row * DD);
    float4 v = xr[threadIdx.x];

    float s  = v.x + v.y + v.z + v.w;
    float sq = v.x*v.x + v.y*v.y + v.z*v.z + v.w*v.w;
    #pragma unroll
    for (int o = 16; o > 0; o >>= 1) {
        s  += __shfl_xor_sync(0xffffffffu, s,  o);
        sq += __shfl_xor_sync(0xffffffffu, sq, o);
    }
    __shared__ float ps[8], psq[8];
    int wid = threadIdx.x >> 5, lane = threadIdx.x & 31;
    if (lane == 0) { ps[wid] = s; psq[wid] = sq; }
    __syncthreads();
    float ts = 0.f, tsq = 0.f;
    #pragma unroll
    for (int i = 0; i < 8; i++) { ts += ps[i]; tsq += psq[i]; }

    float mu   = ts * (1.0f / DD);
    float var  = tsq * (1.0f / DD) - mu * mu;
    float rstd = rsqrtf(var + 1e-5f);

    float4 g = reinterpret_cast<const float4*>(gamma)[threadIdx.x];
    float4 b = reinterpret_cast<const float4*>(beta )[threadIdx.x];
    float o0 = (v.x - mu) * rstd * g.x + b.x;
    float o1 = (v.y - mu) * rstd * g.y + b.y;
    float o2 = (v.z - mu) * rstd * g.z + b.z;
    float o3 = (v.w - mu) * rstd * g.w + b.w;

    unsigned short h0,h1,h2,h3, l0,l1,l2,l3;
    split1(o0,h0,l0); split1(o1,h1,l1); split1(o2,h2,l2); split1(o3,h3,l3);
    uint2 hv = make_uint2((uint32_t)h0 | ((uint32_t)h1<<16), (uint32_t)h2 | ((uint32_t)h3<<16));
    uint2 lv = make_uint2((uint32_t)l0 | ((uint32_t)l1<<16), (uint32_t)l2 | ((uint32_t)l3<<16));
    reinterpret_cast<uint2*>(oh + (size_t)row*DD)[threadIdx.x] = hv;
    reinterpret_cast<uint2*>(ol + (size_t)row*DD)[threadIdx.x] = lv;
}

// ---------------- all-weights transpose + split (single launch) ----------------
__global__ __launch_bounds__(256) void wsplit_all(
    const float* __restrict__ Wq, const float* __restrict__ Wk,
    const float* __restrict__ Wv, const float* __restrict__ Wo,
    const float* __restrict__ W1, const float* __restrict__ W2,
    __nv_bfloat16* __restrict__ qkvth, __nv_bfloat16* __restrict__ qkvtl,
    __nv_bfloat16* __restrict__ woth,  __nv_bfloat16* __restrict__ wotl,
    __nv_bfloat16* __restrict__ w1th,  __nv_bfloat16* __restrict__ w1tl,
    __nv_bfloat16* __restrict__ w2th,  __nv_bfloat16* __restrict__ w2tl)
{
    int z = blockIdx.z;
    const float* W;
    __nv_bfloat16 *Bh, *Bl;
    int K, N, n0, k0;
    if (z < 4) {
        W  = (z==0) ? Wq : (z==1) ? Wk : (z==2) ? Wv : Wo;
        Bh = (z<3) ? qkvth + (size_t)z*DD*DD : woth;
        Bl = (z<3) ? qkvtl + (size_t)z*DD*DD : wotl;
        K = DD; N = DD;
        n0 = blockIdx.x * 32; k0 = blockIdx.y * 32;
    } else if (z < 8) {
        W = W1; Bh = w1th; Bl = w1tl; K = DD; N = FF;
        n0 = (z-4)*1024 + blockIdx.x * 32; k0 = blockIdx.y * 32;
    } else {
        W = W2; Bh = w2th; Bl = w2tl; K = FF; N = DD;
        n0 = blockIdx.x * 32; k0 = (z-8)*1024 + blockIdx.y * 32;
    }

    __shared__ float t[32][33];
    int tx = threadIdx.x & 31, ty = threadIdx.x >> 5;
    #pragma unroll
    for (int r = 0; r < 4; r++)
        t[ty + 8*r][tx] = W[(size_t)(k0 + ty + 8*r) * N + n0 + tx];
    __syncthreads();
    #pragma unroll
    for (int r = 0; r < 4; r++) {
        int n = ty + 8*r, k = tx;
        float x = t[k][n];
        unsigned short h, l;
        split1(x, h, l);
        size_t o = (size_t)(n0 + n) * K + k0 + k;
        Bh[o] = __ushort_as_bfloat16(h);
        Bl[o] = __ushort_as_bfloat16(l);
    }
}

// ---------------- concat q/k/v biases ----------------
__global__ void bias3(const float* a, const float* b, const float* c, float* o) {
    int i = blockIdx.x * 256 + threadIdx.x;
    o[i] = (i < DD) ? a[i] : (i < 2*DD) ? b[i - DD] : c[i - 2*DD];
}

// ---------------- split-bf16 warp-MMA GEMM: BK=32, 3-stage, 2 CTAs/SM ----------------
#define MBK 32
#define SOFF_AHI 0
#define SOFF_ALO 8192
#define SOFF_BHI 16384
#define SOFF_BLO 24576
#define MSTAGE 32768
#define MSMEM (3*MSTAGE)

#define MODE_QKV3       1
#define MODE_RESID      2
#define MODE_RELU_SPLIT 3

__global__ __launch_bounds__(256, 2) void gemm_mma(
    const __nv_bfloat16* __restrict__ Ah, const __nv_bfloat16* __restrict__ Al,
    const __nv_bfloat16* __restrict__ Bh, const __nv_bfloat16* __restrict__ Bl,
    const float* __restrict__ bias, const float* __restrict__ resid,
    float* __restrict__ Cf, __nv_bfloat16* __restrict__ Ch, __nv_bfloat16* __restrict__ Cl,
    int M, int K, int N, int mode)
{
    extern __shared__ char smraw[];
    const uint32_t smbase = smem_u32(smraw);

    const int tid  = threadIdx.x;
    const int warp = tid >> 5;
    const int lane = tid & 31;
    const int warpMoff = (warp & 1) * 64;
    const int warpNoff = (warp >> 1) * 32;
    const int mBase = blockIdx.y * 128;
    const int nBase = blockIdx.x * 128;
    const int nk = K / MBK;

    const int g = lane >> 3, l8 = lane & 7;
    uint32_t aoff[2][4], boff[2][2];
    #pragma unroll
    for (int ks = 0; ks < 2; ks++) {
        #pragma unroll
        for (int mt = 0; mt < 4; mt++)
            aoff[ks][mt] = tile_off(warpMoff + mt*16 + (g & 1)*8 + l8, 2*ks + (g >> 1));
        #pragma unroll
        for (int p = 0; p < 2; p++)
            boff[ks][p]  = tile_off(warpNoff + p*16 + (g >> 1)*8 + l8, 2*ks + (g & 1));
    }

    auto load_stage = [&](int chunk, int s) {
        const int k0 = chunk * MBK;
        uint32_t sb = smbase + (uint32_t)s * MSTAGE;
        #pragma unroll
        for (int h = 0; h < 2; h++) {
            int id = tid + h * 256;
            int r = id >> 2, c = id & 3;
            uint32_t so = tile_off(r, c);
            size_t ga = ((size_t)(mBase + r) * K + k0 + c*8) * 2;
            size_t gb = ((size_t)(nBase + r) * K + k0 + c*8) * 2;
            cp16(sb + SOFF_AHI + so, (const char*)Ah + ga);
            cp16(sb + SOFF_ALO + so, (const char*)Al + ga);
            cp16(sb + SOFF_BHI + so, (const char*)Bh + gb);
            cp16(sb + SOFF_BLO + so, (const char*)Bl + gb);
        }
        cp_commit();
    };

    load_stage(0, 0);
    load_stage(1, 1);
    load_stage(2, 2);

    float acc[4][4][4];
    #pragma unroll
    for (int mt = 0; mt < 4; mt++)
        #pragma unroll
        for (int nt = 0; nt < 4; nt++)
            #pragma unroll
            for (int e = 0; e < 4; e++) acc[mt][nt][e] = 0.f;

    for (int chunk = 0; chunk < nk; chunk++) {
        const int s = chunk % 3;
        const int rem = nk - 1 - chunk;
        if (rem >= 2)      asm volatile("cp.async.wait_group 2;" ::: "memory");
        else if (rem == 1) asm volatile("cp.async.wait_group 1;" ::: "memory");
        else               asm volatile("cp.async.wait_group 0;" ::: "memory");
        __syncthreads();

        const uint32_t sb = smbase + (uint32_t)s * MSTAGE;
        #pragma unroll
        for (int ks = 0; ks < 2; ks++) {
            // B fragments first (shared across all m-tiles)
            uint32_t bhi[4][2], blo[4][2];
            #pragma unroll
            for (int p = 0; p < 2; p++) {
                ldsm4(&bhi[2*p][0], sb + SOFF_BHI + boff[ks][p]);
                ldsm4(&blo[2*p][0], sb + SOFF_BLO + boff[ks][p]);
            }
            // per m-tile: load A hi/lo, issue its 12 MMAs immediately (low live-reg)
            #pragma unroll
            for (int mt = 0; mt < 4; mt++) {
                uint32_t ahi[4], alo[4];
                ldsm4(ahi, sb + SOFF_AHI + aoff[ks][mt]);
                ldsm4(alo, sb + SOFF_ALO + aoff[ks][mt]);
                #pragma unroll
                for (int nt = 0; nt < 4; nt++) {
                    mma_bf16(acc[mt][nt], ahi, bhi[nt]);
                    mma_bf16(acc[mt][nt], ahi, blo[nt]);
                    mma_bf16(acc[mt][nt], alo, bhi[nt]);
                }
            }
        }
        __syncthreads();
        if (chunk + 3 < nk) load_stage(chunk + 3, s);
    }

    // ---------------- epilogue ----------------
    const int rl = lane >> 2;
    const int cl = (lane & 3) * 2;

    #pragma unroll
    for (int mt = 0; mt < 4; mt++) {
        #pragma unroll
        for (int nt = 0; nt < 4; nt++) {
            int gr0 = mBase + warpMoff + mt*16 + rl;
            int gc  = nBase + warpNoff + nt*8 + cl;
            float b0 = __ldg(&bias[gc]);
            float b1 = __ldg(&bias[gc + 1]);
            float v00 = acc[mt][nt][0] + b0, v01 = acc[mt][nt][1] + b1;
            float v10 = acc[mt][nt][2] + b0, v11 = acc[mt][nt][3] + b1;

            if (mode == MODE_QKV3) {
                int t = gc >> 10;
                int within = gc & 1023;
                int h = within >> 6, jj = within & 63;
                int p = jj >> 1;
                float inv = expf(-0.28782313663f * (float)p);   // 10000^(-p/32)
                #pragma unroll
                for (int rr = 0; rr < 2; rr++) {
                    int row = gr0 + rr*8;
                    int b = row >> 11, sI = row & 2047;
                    float w0 = rr ? v10 : v00;
                    float w1 = rr ? v11 : v01;
                    if (t < 2) {
                        float sn, cs;
                        sincosf((float)sI * inv, &sn, &cs);
                        float r0 = w0 * cs - w1 * sn;
                        float r1 = w0 * sn + w1 * cs;
                        if (t == 0) { r0 *= 0.125f; r1 *= 0.125f; }
                        w0 = r0; w1 = r1;
                    }
                    unsigned short h0,l0,h1,l1;
                    split1(w0, h0, l0);
                    split1(w1, h1, l1);
                    size_t ob = (size_t)t * NN * DD +
                                ((size_t)((b*HH + h)*SS + sI)) * HD + jj;
                    reinterpret_cast<uint32_t*>(Ch)[ob >> 1] = (uint32_t)h0 | ((uint32_t)h1 << 16);
                    reinterpret_cast<uint32_t*>(Cl)[ob >> 1] = (uint32_t)l0 | ((uint32_t)l1 << 16);
                }
            } else if (mode == MODE_RESID) {
                #pragma unroll
                for (int rr = 0; rr < 2; rr++) {
                    int row = gr0 + rr*8;
                    size_t ob = (size_t)row * N + gc;
                    float2 rv = *reinterpret_cast<const float2*>(resid + ob);
                    float2 o = rr ? make_float2(v10 + rv.x, v11 + rv.y)
                                  : make_float2(v00 + rv.x, v01 + rv.y);
                    *reinterpret_cast<float2*>(Cf + ob) = o;
                }
            } else { // MODE_RELU_SPLIT
                #pragma unroll
                for (int rr = 0; rr < 2; rr++) {
                    int row = gr0 + rr*8;
                    size_t ob = (size_t)row * N + gc;
                    float w0 = fmaxf(rr ? v10 : v00, 0.f);
                    float w1 = fmaxf(rr ? v11 : v01, 0.f);
                    unsigned short h0,l0,h1,l1;
                    split1(w0, h0, l0);
                    split1(w1, h1, l1);
                    reinterpret_cast<uint32_t*>(Ch)[ob >> 1] = (uint32_t)h0 | ((uint32_t)h1 << 16);
                    reinterpret_cast<uint32_t*>(Cl)[ob >> 1] = (uint32_t)l0 | ((uint32_t)l1 << 16);
                }
            }
        }
    }
}

// ---------------- split-bf16 MMA flash attention (V row-major + ldmatrix.trans) ----------------
#define AT_SQH   0
#define AT_SQL   16384
#define AT_STAGE 32768
#define AT_SSZ   32768
#define AT_KH    0
#define AT_KL    8192
#define AT_VH    16384
#define AT_VL    24576
#define ATTN_SMEM (32768 + 2*32768)

__global__ __launch_bounds__(256, 2) void attn_mma(
    const __nv_bfloat16* __restrict__ Qh, const __nv_bfloat16* __restrict__ Ql,
    const __nv_bfloat16* __restrict__ Kh, const __nv_bfloat16* __restrict__ Kl,
    const __nv_bfloat16* __restrict__ Vh, const __nv_bfloat16* __restrict__ Vl,
    __nv_bfloat16* __restrict__ Oh, __nv_bfloat16* __restrict__ Ol)
{
    extern __shared__ char smraw[];
    const uint32_t sm = smem_u32(smraw);
    const int tid = threadIdx.x, warp = tid >> 5, lane = tid & 31;
    const int bh = blockIdx.y;
    const int q0 = blockIdx.x * 128;
    const int g = lane >> 3, l8 = lane & 7;
    const int rl = lane >> 2, cl = (lane & 3) * 2;

    // load Q tiles (hi/lo), part of first commit group
    #pragma unroll
    for (int t = 0; t < 8; t++) {
        int buf = t >> 2;                    // 0=hi,1=lo
        int w = (t & 3) * 256 + tid;         // 0..1023
        int r = w >> 3, c = w & 7;
        uint32_t off = (buf ? AT_SQL : AT_SQH) + (c >> 2) * 8192 + tile_off(r, c & 3);
        const char* gp = (const char*)(buf ? Ql : Qh) +
                         ((size_t)((size_t)bh * SS + q0 + r) * HD + c * 8) * 2;
        cp16(sm + off, gp);
    }

    auto load_kv = [&](int kb, int s) {
        uint32_t sb = sm + AT_STAGE + (uint32_t)s * AT_SSZ;
        #pragma unroll
        for (int t = 0; t < 8; t++) {
            int buf = t >> 1;                // 0=Kh 1=Kl 2=Vh 3=Vl
            int w = (t & 1) * 256 + tid;     // 0..511
            int r = w >> 3, c = w & 7;
            uint32_t off = (uint32_t)buf * 8192 + (c >> 2) * 4096 + tile_off(r, c & 3);
            const __nv_bfloat16* src = (buf == 0) ? Kh : (buf == 1) ? Kl : (buf == 2) ? Vh : Vl;
            const char* gp = (const char*)src + ((size_t)((size_t)bh * SS + kb + r) * HD + c * 8) * 2;
            cp16(sb + off, gp);
        }
        cp_commit();
    };

    load_kv(0, 0);
    load_kv(64, 1);

    float m0 = -1e30f, m1 = -1e30f, l0 = 0.f, l1 = 0.f;
    float acc[8][4];
    #pragma unroll
    for (int nt = 0; nt < 8; nt++)
        #pragma unroll
        for (int e = 0; e < 4; e++) acc[nt][e] = 0.f;

    const int NT = SS / 64;
    for (int it = 0; it < NT; it++) {
        if (it + 1 < NT) asm volatile("cp.async.wait_group 1;" ::: "memory");
        else             asm volatile("cp.async.wait_group 0;" ::: "memory");
        __syncthreads();
        const uint32_t sb = sm + AT_STAGE + (uint32_t)(it & 1) * AT_SSZ;

        // ---- S = Q K^T (split 3-product) ----
        float sacc[8][4];
        #pragma unroll
        for (int nt = 0; nt < 8; nt++)
            #pragma unroll
            for (int e = 0; e < 4; e++) sacc[nt][e] = 0.f;

        #pragma unroll
        for (int ks = 0; ks < 4; ks++) {
            uint32_t qoff = (uint32_t)((ks >> 1) * 8192) +
                            tile_off(warp*16 + (g & 1)*8 + l8, 2*(ks & 1) + (g >> 1));
            uint32_t qh4[4], ql4[4];
            ldsm4(qh4, sm + AT_SQH + qoff);
            ldsm4(ql4, sm + AT_SQL + qoff);
            uint32_t kh4[4][4], kl4[4][4];
            #pragma unroll
            for (int p = 0; p < 4; p++) {
                uint32_t ko = (uint32_t)((ks >> 1) * 4096) +
                              tile_off(p*16 + (g >> 1)*8 + l8, 2*(ks & 1) + (g & 1));
                ldsm4(kh4[p], sb + AT_KH + ko);
                ldsm4(kl4[p], sb + AT_KL + ko);
            }
            #pragma unroll
            for (int nt = 0; nt < 8; nt++) {
                const uint32_t* bhk = &kh4[nt >> 1][(nt & 1) * 2];
                const uint32_t* blk = &kl4[nt >> 1][(nt & 1) * 2];
                mma_bf16(sacc[nt], qh4, bhk);
                mma_bf16(sacc[nt], qh4, blk);
                mma_bf16(sacc[nt], ql4, bhk);
            }
        }

        // ---- online softmax ----
        float mx0 = -1e30f, mx1 = -1e30f;
        #pragma unroll
        for (int nt = 0; nt < 8; nt++) {
            mx0 = fmaxf(mx0, fmaxf(sacc[nt][0], sacc[nt][1]));
            mx1 = fmaxf(mx1, fmaxf(sacc[nt][2], sacc[nt][3]));
        }
        mx0 = fmaxf(mx0, __shfl_xor_sync(0xffffffffu, mx0, 1));
        mx0 = fmaxf(mx0, __shfl_xor_sync(0xffffffffu, mx0, 2));
        mx1 = fmaxf(mx1, __shfl_xor_sync(0xffffffffu, mx1, 1));
        mx1 = fmaxf(mx1, __shfl_xor_sync(0xffffffffu, mx1, 2));

        float mn0 = fmaxf(m0, mx0), mn1 = fmaxf(m1, mx1);
        float a0 = __expf(m0 - mn0), a1 = __expf(m1 - mn1);
        float rs0 = 0.f, rs1 = 0.f;
        #pragma unroll
        for (int nt = 0; nt < 8; nt++) {
            sacc[nt][0] = __expf(sacc[nt][0] - mn0);
            sacc[nt][1] = __expf(sacc[nt][1] - mn0);
            sacc[nt][2] = __expf(sacc[nt][2] - mn1);
            sacc[nt][3] = __expf(sacc[nt][3] - mn1);
            rs0 += sacc[nt][0] + sacc[nt][1];
            rs1 += sacc[nt][2] + sacc[nt][3];
        }
        rs0 += __shfl_xor_sync(0xffffffffu, rs0, 1);
        rs0 += __shfl_xor_sync(0xffffffffu, rs0, 2);
        rs1 += __shfl_xor_sync(0xffffffffu, rs1, 1);
        rs1 += __shfl_xor_sync(0xffffffffu, rs1, 2);
        l0 = l0 * a0 + rs0;  m0 = mn0;
        l1 = l1 * a1 + rs1;  m1 = mn1;
        #pragma unroll
        for (int nt = 0; nt < 8; nt++) {
            acc[nt][0] *= a0; acc[nt][1] *= a0;
            acc[nt][2] *= a1; acc[nt][3] *= a1;
        }

        // ---- O += P V (split 3-product); V row-major, trans ldmatrix ----
        #pragma unroll
        for (int ks = 0; ks < 4; ks++) {
            uint32_t aH[4], aL[4];
            #pragma unroll
            for (int half = 0; half < 2; half++) {
                int nt = 2*ks + half;
                unsigned short h0,l0s,h1,l1s,h2,l2s,h3,l3s;
                split1(sacc[nt][0], h0, l0s);
                split1(sacc[nt][1], h1, l1s);
                split1(sacc[nt][2], h2, l2s);
                split1(sacc[nt][3], h3, l3s);
                aH[half*2 + 0] = (uint32_t)h0  | ((uint32_t)h1  << 16);
                aH[half*2 + 1] = (uint32_t)h2  | ((uint32_t)h3  << 16);
                aL[half*2 + 0] = (uint32_t)l0s | ((uint32_t)l1s << 16);
                aL[half*2 + 1] = (uint32_t)l2s | ((uint32_t)l3s << 16);
            }
            uint32_t vh4[4][4], vl4[4][4];
            int vrow = 16*ks + (g & 1)*8 + l8;
            #pragma unroll
            for (int p = 0; p < 4; p++) {
                int c = p*2 + (g >> 1);            // 16B d-chunk 0..7
                uint32_t vo = (uint32_t)((c >> 2) * 4096) + tile_off(vrow, c & 3);
                ldsm4t(vh4[p], sb + AT_VH + vo);
                ldsm4t(vl4[p], sb + AT_VL + vo);
            }
            #pragma unroll
            for (int nt = 0; nt < 8; nt++) {
                const uint32_t* bhv = &vh4[nt >> 1][(nt & 1) * 2];
                const uint32_t* blv = &vl4[nt >> 1][(nt & 1) * 2];
                mma_bf16(acc[nt], aH, bhv);
                mma_bf16(acc[nt], aL, bhv);
                mma_bf16(acc[nt], aH, blv);
            }
        }

        __syncthreads();
        if (it + 2 < NT) load_kv((it + 2) * 64, it & 1);
    }

    // ---- epilogue: normalize, split to bf16 hi/lo, write [B,S,D] ----
    float i0 = 1.f / l0, i1 = 1.f / l1;
    int b = bh >> 4, h = bh & 15;
    int s0r = q0 + warp * 16 + rl;
    #pragma unroll
    for (int nt = 0; nt < 8; nt++) {
        int col = h * 64 + nt * 8 + cl;
        {
            float w0 = acc[nt][0] * i0, w1 = acc[nt][1] * i0;
            unsigned short h0,lo0,h1,lo1;
            split1(w0, h0, lo0); split1(w1, h1, lo1);
            size_t ob = (size_t)(b * SS + s0r) * DD + col;
            reinterpret_cast<uint32_t*>(Oh)[ob >> 1] = (uint32_t)h0  | ((uint32_t)h1  << 16);
            reinterpret_cast<uint32_t*>(Ol)[ob >> 1] = (uint32_t)lo0 | ((uint32_t)lo1 << 16);
        }
        {
            float w0 = acc[nt][2] * i1, w1 = acc[nt][3] * i1;
            unsigned short h0,lo0,h1,lo1;
            split1(w0, h0, lo0); split1(w1, h1, lo1);
            size_t ob = (size_t)(b * SS + s0r + 8) * DD + col;
            reinterpret_cast<uint32_t*>(Oh)[ob >> 1] = (uint32_t)h0  | ((uint32_t)h1  << 16);
            reinterpret_cast<uint32_t*>(Ol)[ob >> 1] = (uint32_t)lo0 | ((uint32_t)lo1 << 16);
        }
    }
}

// ---------------- host launch ----------------
extern "C" void kernel_launch(void* const* d_in, const int* in_sizes, int n_in,
                              void* d_out, int out_size)
{
    const float* x     = (const float*)d_in[0];
    const float* Wq    = (const float*)d_in[1];
    const float* bq    = (const float*)d_in[2];
    const float* Wk    = (const float*)d_in[3];
    const float* bk    = (const float*)d_in[4];
    const float* Wv    = (const float*)d_in[5];
    const float* bv    = (const float*)d_in[6];
    const float* Wo    = (const float*)d_in[7];
    const float* bo    = (const float*)d_in[8];
    const float* W1    = (const float*)d_in[9];
    const float* b1    = (const float*)d_in[10];
    const float* W2    = (const float*)d_in[11];
    const float* b2    = (const float*)d_in[12];
    const float* g1    = (const float*)d_in[13];
    const float* beta1 = (const float*)d_in[14];
    const float* g2    = (const float*)d_in[15];
    const float* beta2 = (const float*)d_in[16];
    float* out = (float*)d_out;

    float *x1, *bqkv;
    __nv_bfloat16 *xnh, *xnl, *xn2h, *xn2l, *ath, *atl, *hh, *hl;
    __nv_bfloat16 *qkvbh, *qkvbl;
    __nv_bfloat16 *qkvth, *qkvtl, *woth, *wotl, *w1th, *w1tl, *w2th, *w2tl;
    cudaGetSymbolAddress((void**)&x1,    g_x1);
    cudaGetSymbolAddress((void**)&bqkv,  g_bqkv);
    cudaGetSymbolAddress((void**)&xnh,   g_xn_h);
    cudaGetSymbolAddress((void**)&xnl,   g_xn_l);
    cudaGetSymbolAddress((void**)&xn2h,  g_xn2_h);
    cudaGetSymbolAddress((void**)&xn2l,  g_xn2_l);
    cudaGetSymbolAddress((void**)&ath,   g_at_h);
    cudaGetSymbolAddress((void**)&atl,   g_at_l);
    cudaGetSymbolAddress((void**)&hh,    g_h_h);
    cudaGetSymbolAddress((void**)&hl,    g_h_l);
    cudaGetSymbolAddress((void**)&qkvbh, g_qkvb_h);
    cudaGetSymbolAddress((void**)&qkvbl, g_qkvb_l);
    cudaGetSymbolAddress((void**)&qkvth, g_qkvt_h);
    cudaGetSymbolAddress((void**)&qkvtl, g_qkvt_l);
    cudaGetSymbolAddress((void**)&woth,  g_wot_h);
    cudaGetSymbolAddress((void**)&wotl,  g_wot_l);
    cudaGetSymbolAddress((void**)&w1th,  g_w1t_h);
    cudaGetSymbolAddress((void**)&w1tl,  g_w1t_l);
    cudaGetSymbolAddress((void**)&w2th,  g_w2t_h);
    cudaGetSymbolAddress((void**)&w2tl,  g_w2t_l);

    cudaFuncSetAttribute(gemm_mma, cudaFuncAttributeMaxDynamicSharedMemorySize, MSMEM);
    cudaFuncSetAttribute(attn_mma, cudaFuncAttributeMaxDynamicSharedMemorySize, ATTN_SMEM);

    // 1: all weight transposes + splits in one launch
    wsplit_all<<<dim3(32, 32, 12), 256>>>(Wq, Wk, Wv, Wo, W1, W2,
                                          qkvth, qkvtl, woth, wotl,
                                          w1th, w1tl, w2th, w2tl);
    // 2
    bias3<<<3*DD/256, 256>>>(bq, bk, bv, bqkv);
    // 3: LN1 -> split
    ln_split<<<NN, 256>>>(x, g1, beta1, xnh, xnl);

    // 4: fused QKV projection + bias + RoPE + split (q,k,v bf16 hi/lo)
    gemm_mma<<<dim3(3*DD/128, NN/128), 256, MSMEM>>>(
        xnh, xnl, qkvth, qkvtl, bqkv, nullptr, nullptr, qkvbh, qkvbl,
        NN, DD, 3*DD, MODE_QKV3);

    __nv_bfloat16* qh = qkvbh;
    __nv_bfloat16* ql = qkvbl;
    __nv_bfloat16* kh = qkvbh + (size_t)NN*DD;
    __nv_bfloat16* kl = qkvbl + (size_t)NN*DD;
    __nv_bfloat16* vh = qkvbh + 2*(size_t)NN*DD;
    __nv_bfloat16* vl = qkvbl + 2*(size_t)NN*DD;

    // 5: MMA flash attention -> bf16 hi/lo attn output [B,S,D]
    attn_mma<<<dim3(SS/128, BB*HH), 256, ATTN_SMEM>>>(qh, ql, kh, kl, vh, vl, ath, atl);

    // 6: x1 = x + attn @ Wo + bo
    gemm_mma<<<dim3(DD/128, NN/128), 256, MSMEM>>>(
        ath, atl, woth, wotl, bo, x, x1, nullptr, nullptr,
        NN, DD, DD, MODE_RESID);

    // 7: LN2 -> split
    ln_split<<<NN, 256>>>(x1, g2, beta2, xn2h, xn2l);

    // 8: FFN up: relu + split epilogue
    gemm_mma<<<dim3(FF/128, NN/128), 256, MSMEM>>>(
        xn2h, xn2l, w1th, w1tl, b1, nullptr, nullptr, hh, hl,
        NN, DD, FF, MODE_RELU_SPLIT);

    // 9: FFN down + residual -> out
    gemm_mma<<<dim3(DD/128, NN/128), 256, MSMEM>>>(
        hh, hl, w2th, w2tl, b2, x1, out, nullptr, nullptr,
        NN, FF, DD, MODE_RESID);
}

// round 9
// speedup vs baseline: 3.3116x; 1.0362x over previous
#include <cuda_runtime.h>
#include <cuda_bf16.h>
#include <math.h>
#include <stdint.h>

#define BB 2
#define SS 2048
#define DD 1024
#define HH 16
#define HD 64
#define FF 4096
#define NN (BB*SS)   // 4096 tokens

// ---------------- scratch (static device globals; no allocs) ----------------
__device__ float g_x1  [NN*DD];      // x + attn_out
__device__ __nv_bfloat16 g_xn_h [NN*DD], g_xn_l [NN*DD];
__device__ __nv_bfloat16 g_xn2_h[NN*DD], g_xn2_l[NN*DD];
__device__ __nv_bfloat16 g_at_h [NN*DD], g_at_l [NN*DD];   // attn out [B,S,D]
__device__ __nv_bfloat16 g_qkvb_h[3u*NN*DD], g_qkvb_l[3u*NN*DD]; // q,k,v [t][B,H,S,hd]
__device__ __nv_bfloat16 g_h_h  [(size_t)NN*FF], g_h_l[(size_t)NN*FF];
__device__ __nv_bfloat16 g_qkvt_h[3*DD*DD], g_qkvt_l[3*DD*DD]; // [3072,1024]
__device__ __nv_bfloat16 g_wot_h [DD*DD],   g_wot_l [DD*DD];
__device__ __nv_bfloat16 g_w1t_h [FF*DD],   g_w1t_l [FF*DD];
__device__ __nv_bfloat16 g_w2t_h [DD*FF],   g_w2t_l [DD*FF];
__device__ float g_bqkv[3*DD];

// ---------------- helpers ----------------
__device__ __forceinline__ uint32_t smem_u32(const void* p) {
    return (uint32_t)__cvta_generic_to_shared(p);
}
__device__ __forceinline__ void cp16(uint32_t s, const void* g) {
    asm volatile("cp.async.cg.shared.global [%0], [%1], 16;" :: "r"(s), "l"(g));
}
__device__ __forceinline__ void cp_commit() {
    asm volatile("cp.async.commit_group;" ::: "memory");
}
__device__ __forceinline__ void ldsm4(uint32_t* r, uint32_t addr) {
    asm volatile("ldmatrix.sync.aligned.m8n8.x4.shared.b16 {%0,%1,%2,%3}, [%4];"
        : "=r"(r[0]), "=r"(r[1]), "=r"(r[2]), "=r"(r[3]) : "r"(addr));
}
__device__ __forceinline__ void ldsm4t(uint32_t* r, uint32_t addr) {
    asm volatile("ldmatrix.sync.aligned.m8n8.x4.trans.shared.b16 {%0,%1,%2,%3}, [%4];"
        : "=r"(r[0]), "=r"(r[1]), "=r"(r[2]), "=r"(r[3]) : "r"(addr));
}
__device__ __forceinline__ void mma_bf16(float* d, const uint32_t* a, const uint32_t* b) {
    asm volatile("mma.sync.aligned.m16n8k16.row.col.f32.bf16.bf16.f32 "
        "{%0,%1,%2,%3}, {%4,%5,%6,%7}, {%8,%9}, {%0,%1,%2,%3};"
        : "+f"(d[0]), "+f"(d[1]), "+f"(d[2]), "+f"(d[3])
        : "r"(a[0]), "r"(a[1]), "r"(a[2]), "r"(a[3]), "r"(b[0]), "r"(b[1]));
}
__device__ __forceinline__ void split1(float x, unsigned short& h, unsigned short& l) {
    __nv_bfloat16 hb = __float2bfloat16(x);
    float hf = __bfloat162float(hb);
    __nv_bfloat16 lb = __float2bfloat16(x - hf);
    h = __bfloat16_as_ushort(hb);
    l = __bfloat16_as_ushort(lb);
}
// swizzled offset inside a 64B-wide tile: (row, 16B-chunk c in 0..3)
__device__ __forceinline__ uint32_t tile_off(int r, int c) {
    return (uint32_t)(((r >> 1) * 128) + (((((r & 1) << 2) | c) ^ ((r >> 1) & 7)) << 4));
}

// ---------------- LayerNorm with bf16 hi/lo split output ----------------
__global__ __launch_bounds__(256) void ln_split(const float* __restrict__ x,
                                                const float* __restrict__ gamma,
                                                const float* __restrict__ beta,
                                                __nv_bfloat16* __restrict__ oh,
                                                __nv_bfloat16* __restrict__ ol)
{
    int row = blockIdx.x;
    const float4* xr = reinterpret_cast<const float4*>(x + (size_t)row * DD);
    float4 v = xr[threadIdx.x];

    float s  = v.x + v.y + v.z + v.w;
    float sq = v.x*v.x + v.y*v.y + v.z*v.z + v.w*v.w;
    #pragma unroll
    for (int o = 16; o > 0; o >>= 1) {
        s  += __shfl_xor_sync(0xffffffffu, s,  o);
        sq += __shfl_xor_sync(0xffffffffu, sq, o);
    }
    __shared__ float ps[8], psq[8];
    int wid = threadIdx.x >> 5, lane = threadIdx.x & 31;
    if (lane == 0) { ps[wid] = s; psq[wid] = sq; }
    __syncthreads();
    float ts = 0.f, tsq = 0.f;
    #pragma unroll
    for (int i = 0; i < 8; i++) { ts += ps[i]; tsq += psq[i]; }

    float mu   = ts * (1.0f / DD);
    float var  = tsq * (1.0f / DD) - mu * mu;
    float rstd = rsqrtf(var + 1e-5f);

    float4 g = reinterpret_cast<const float4*>(gamma)[threadIdx.x];
    float4 b = reinterpret_cast<const float4*>(beta )[threadIdx.x];
    float o0 = (v.x - mu) * rstd * g.x + b.x;
    float o1 = (v.y - mu) * rstd * g.y + b.y;
    float o2 = (v.z - mu) * rstd * g.z + b.z;
    float o3 = (v.w - mu) * rstd * g.w + b.w;

    unsigned short h0,h1,h2,h3, l0,l1,l2,l3;
    split1(o0,h0,l0); split1(o1,h1,l1); split1(o2,h2,l2); split1(o3,h3,l3);
    uint2 hv = make_uint2((uint32_t)h0 | ((uint32_t)h1<<16), (uint32_t)h2 | ((uint32_t)h3<<16));
    uint2 lv = make_uint2((uint32_t)l0 | ((uint32_t)l1<<16), (uint32_t)l2 | ((uint32_t)l3<<16));
    reinterpret_cast<uint2*>(oh + (size_t)row*DD)[threadIdx.x] = hv;
    reinterpret_cast<uint2*>(ol + (size_t)row*DD)[threadIdx.x] = lv;
}

// ---------------- all-weights transpose + split (single launch) ----------------
__global__ __launch_bounds__(256) void wsplit_all(
    const float* __restrict__ Wq, const float* __restrict__ Wk,
    const float* __restrict__ Wv, const float* __restrict__ Wo,
    const float* __restrict__ W1, const float* __restrict__ W2,
    __nv_bfloat16* __restrict__ qkvth, __nv_bfloat16* __restrict__ qkvtl,
    __nv_bfloat16* __restrict__ woth,  __nv_bfloat16* __restrict__ wotl,
    __nv_bfloat16* __restrict__ w1th,  __nv_bfloat16* __restrict__ w1tl,
    __nv_bfloat16* __restrict__ w2th,  __nv_bfloat16* __restrict__ w2tl)
{
    int z = blockIdx.z;
    const float* W;
    __nv_bfloat16 *Bh, *Bl;
    int K, N, n0, k0;
    if (z < 4) {
        W  = (z==0) ? Wq : (z==1) ? Wk : (z==2) ? Wv : Wo;
        Bh = (z<3) ? qkvth + (size_t)z*DD*DD : woth;
        Bl = (z<3) ? qkvtl + (size_t)z*DD*DD : wotl;
        K = DD; N = DD;
        n0 = blockIdx.x * 32; k0 = blockIdx.y * 32;
    } else if (z < 8) {
        W = W1; Bh = w1th; Bl = w1tl; K = DD; N = FF;
        n0 = (z-4)*1024 + blockIdx.x * 32; k0 = blockIdx.y * 32;
    } else {
        W = W2; Bh = w2th; Bl = w2tl; K = FF; N = DD;
        n0 = blockIdx.x * 32; k0 = (z-8)*1024 + blockIdx.y * 32;
    }

    __shared__ float t[32][33];
    int tx = threadIdx.x & 31, ty = threadIdx.x >> 5;
    #pragma unroll
    for (int r = 0; r < 4; r++)
        t[ty + 8*r][tx] = W[(size_t)(k0 + ty + 8*r) * N + n0 + tx];
    __syncthreads();
    #pragma unroll
    for (int r = 0; r < 4; r++) {
        int n = ty + 8*r, k = tx;
        float x = t[k][n];
        unsigned short h, l;
        split1(x, h, l);
        size_t o = (size_t)(n0 + n) * K + k0 + k;
        Bh[o] = __ushort_as_bfloat16(h);
        Bl[o] = __ushort_as_bfloat16(l);
    }
}

// ---------------- concat q/k/v biases ----------------
__global__ void bias3(const float* a, const float* b, const float* c, float* o) {
    int i = blockIdx.x * 256 + threadIdx.x;
    o[i] = (i < DD) ? a[i] : (i < 2*DD) ? b[i - DD] : c[i - 2*DD];
}

// ---------------- split-bf16 warp-MMA GEMM: BK=32, 3-stage, 1 barrier/chunk ----------------
#define MBK 32
#define SOFF_AHI 0
#define SOFF_ALO 8192
#define SOFF_BHI 16384
#define SOFF_BLO 24576
#define MSTAGE 32768
#define MSMEM (3*MSTAGE)

#define MODE_QKV3       1
#define MODE_RESID      2
#define MODE_RELU_SPLIT 3

__global__ __launch_bounds__(256, 2) void gemm_mma(
    const __nv_bfloat16* __restrict__ Ah, const __nv_bfloat16* __restrict__ Al,
    const __nv_bfloat16* __restrict__ Bh, const __nv_bfloat16* __restrict__ Bl,
    const float* __restrict__ bias, const float* __restrict__ resid,
    float* __restrict__ Cf, __nv_bfloat16* __restrict__ Ch, __nv_bfloat16* __restrict__ Cl,
    int M, int K, int N, int mode)
{
    extern __shared__ char smraw[];
    const uint32_t smbase = smem_u32(smraw);

    const int tid  = threadIdx.x;
    const int warp = tid >> 5;
    const int lane = tid & 31;
    const int warpMoff = (warp & 1) * 64;
    const int warpNoff = (warp >> 1) * 32;
    const int mBase = blockIdx.y * 128;
    const int nBase = blockIdx.x * 128;
    const int nk = K / MBK;

    const int g = lane >> 3, l8 = lane & 7;
    uint32_t aoff[2][4], boff[2][2];
    #pragma unroll
    for (int ks = 0; ks < 2; ks++) {
        #pragma unroll
        for (int mt = 0; mt < 4; mt++)
            aoff[ks][mt] = tile_off(warpMoff + mt*16 + (g & 1)*8 + l8, 2*ks + (g >> 1));
        #pragma unroll
        for (int p = 0; p < 2; p++)
            boff[ks][p]  = tile_off(warpNoff + p*16 + (g >> 1)*8 + l8, 2*ks + (g & 1));
    }

    auto load_stage = [&](int chunk, int s) {
        const int k0 = chunk * MBK;
        uint32_t sb = smbase + (uint32_t)s * MSTAGE;
        #pragma unroll
        for (int h = 0; h < 2; h++) {
            int id = tid + h * 256;
            int r = id >> 2, c = id & 3;
            uint32_t so = tile_off(r, c);
            size_t ga = ((size_t)(mBase + r) * K + k0 + c*8) * 2;
            size_t gb = ((size_t)(nBase + r) * K + k0 + c*8) * 2;
            cp16(sb + SOFF_AHI + so, (const char*)Ah + ga);
            cp16(sb + SOFF_ALO + so, (const char*)Al + ga);
            cp16(sb + SOFF_BHI + so, (const char*)Bh + gb);
            cp16(sb + SOFF_BLO + so, (const char*)Bl + gb);
        }
        cp_commit();
    };

    // 2-deep prefetch into a 3-stage ring
    load_stage(0, 0);
    load_stage(1, 1);

    float acc[4][4][4];
    #pragma unroll
    for (int mt = 0; mt < 4; mt++)
        #pragma unroll
        for (int nt = 0; nt < 4; nt++)
            #pragma unroll
            for (int e = 0; e < 4; e++) acc[mt][nt][e] = 0.f;

    for (int chunk = 0; chunk < nk; chunk++) {
        const int s = chunk % 3;
        if (chunk + 1 < nk) asm volatile("cp.async.wait_group 1;" ::: "memory");
        else                asm volatile("cp.async.wait_group 0;" ::: "memory");
        __syncthreads();
        // stage (chunk+2)%3 == (chunk-1)%3 was drained by this barrier — reload it now,
        // overlapping the copies with this chunk's ldsm/MMA stream.
        if (chunk + 2 < nk) load_stage(chunk + 2, (chunk + 2) % 3);

        const uint32_t sb = smbase + (uint32_t)s * MSTAGE;
        #pragma unroll
        for (int ks = 0; ks < 2; ks++) {
            // B fragments first (shared across all m-tiles)
            uint32_t bhi[4][2], blo[4][2];
            #pragma unroll
            for (int p = 0; p < 2; p++) {
                ldsm4(&bhi[2*p][0], sb + SOFF_BHI + boff[ks][p]);
                ldsm4(&blo[2*p][0], sb + SOFF_BLO + boff[ks][p]);
            }
            // per m-tile: load A hi/lo, issue its 12 MMAs immediately (low live-reg)
            #pragma unroll
            for (int mt = 0; mt < 4; mt++) {
                uint32_t ahi[4], alo[4];
                ldsm4(ahi, sb + SOFF_AHI + aoff[ks][mt]);
                ldsm4(alo, sb + SOFF_ALO + aoff[ks][mt]);
                #pragma unroll
                for (int nt = 0; nt < 4; nt++) {
                    mma_bf16(acc[mt][nt], ahi, bhi[nt]);
                    mma_bf16(acc[mt][nt], ahi, blo[nt]);
                    mma_bf16(acc[mt][nt], alo, bhi[nt]);
                }
            }
        }
        // no trailing barrier: the next iteration's top barrier covers stage reuse
    }

    // ---------------- epilogue ----------------
    const int rl = lane >> 2;
    const int cl = (lane & 3) * 2;

    #pragma unroll
    for (int mt = 0; mt < 4; mt++) {
        #pragma unroll
        for (int nt = 0; nt < 4; nt++) {
            int gr0 = mBase + warpMoff + mt*16 + rl;
            int gc  = nBase + warpNoff + nt*8 + cl;
            float b0 = __ldg(&bias[gc]);
            float b1 = __ldg(&bias[gc + 1]);
            float v00 = acc[mt][nt][0] + b0, v01 = acc[mt][nt][1] + b1;
            float v10 = acc[mt][nt][2] + b0, v11 = acc[mt][nt][3] + b1;

            if (mode == MODE_QKV3) {
                int t = gc >> 10;
                int within = gc & 1023;
                int h = within >> 6, jj = within & 63;
                int p = jj >> 1;
                float inv = expf(-0.28782313663f * (float)p);   // 10000^(-p/32)
                #pragma unroll
                for (int rr = 0; rr < 2; rr++) {
                    int row = gr0 + rr*8;
                    int b = row >> 11, sI = row & 2047;
                    float w0 = rr ? v10 : v00;
                    float w1 = rr ? v11 : v01;
                    if (t < 2) {
                        float sn, cs;
                        sincosf((float)sI * inv, &sn, &cs);
                        float r0 = w0 * cs - w1 * sn;
                        float r1 = w0 * sn + w1 * cs;
                        if (t == 0) { r0 *= 0.125f; r1 *= 0.125f; }
                        w0 = r0; w1 = r1;
                    }
                    unsigned short h0,l0,h1,l1;
                    split1(w0, h0, l0);
                    split1(w1, h1, l1);
                    size_t ob = (size_t)t * NN * DD +
                                ((size_t)((b*HH + h)*SS + sI)) * HD + jj;
                    reinterpret_cast<uint32_t*>(Ch)[ob >> 1] = (uint32_t)h0 | ((uint32_t)h1 << 16);
                    reinterpret_cast<uint32_t*>(Cl)[ob >> 1] = (uint32_t)l0 | ((uint32_t)l1 << 16);
                }
            } else if (mode == MODE_RESID) {
                #pragma unroll
                for (int rr = 0; rr < 2; rr++) {
                    int row = gr0 + rr*8;
                    size_t ob = (size_t)row * N + gc;
                    float2 rv = *reinterpret_cast<const float2*>(resid + ob);
                    float2 o = rr ? make_float2(v10 + rv.x, v11 + rv.y)
                                  : make_float2(v00 + rv.x, v01 + rv.y);
                    *reinterpret_cast<float2*>(Cf + ob) = o;
                }
            } else { // MODE_RELU_SPLIT
                #pragma unroll
                for (int rr = 0; rr < 2; rr++) {
                    int row = gr0 + rr*8;
                    size_t ob = (size_t)row * N + gc;
                    float w0 = fmaxf(rr ? v10 : v00, 0.f);
                    float w1 = fmaxf(rr ? v11 : v01, 0.f);
                    unsigned short h0,l0,h1,l1;
                    split1(w0, h0, l0);
                    split1(w1, h1, l1);
                    reinterpret_cast<uint32_t*>(Ch)[ob >> 1] = (uint32_t)h0 | ((uint32_t)h1 << 16);
                    reinterpret_cast<uint32_t*>(Cl)[ob >> 1] = (uint32_t)l0 | ((uint32_t)l1 << 16);
                }
            }
        }
    }
}

// ---------------- split-bf16 MMA flash attention (V row-major + ldmatrix.trans) ----------------
#define AT_SQH   0
#define AT_SQL   16384
#define AT_STAGE 32768
#define AT_SSZ   32768
#define AT_KH    0
#define AT_KL    8192
#define AT_VH    16384
#define AT_VL    24576
#define ATTN_SMEM (32768 + 2*32768)

__global__ __launch_bounds__(256, 2) void attn_mma(
    const __nv_bfloat16* __restrict__ Qh, const __nv_bfloat16* __restrict__ Ql,
    const __nv_bfloat16* __restrict__ Kh, const __nv_bfloat16* __restrict__ Kl,
    const __nv_bfloat16* __restrict__ Vh, const __nv_bfloat16* __restrict__ Vl,
    __nv_bfloat16* __restrict__ Oh, __nv_bfloat16* __restrict__ Ol)
{
    extern __shared__ char smraw[];
    const uint32_t sm = smem_u32(smraw);
    const int tid = threadIdx.x, warp = tid >> 5, lane = tid & 31;
    const int bh = blockIdx.y;
    const int q0 = blockIdx.x * 128;
    const int g = lane >> 3, l8 = lane & 7;
    const int rl = lane >> 2, cl = (lane & 3) * 2;

    // load Q tiles (hi/lo), part of first commit group
    #pragma unroll
    for (int t = 0; t < 8; t++) {
        int buf = t >> 2;                    // 0=hi,1=lo
        int w = (t & 3) * 256 + tid;         // 0..1023
        int r = w >> 3, c = w & 7;
        uint32_t off = (buf ? AT_SQL : AT_SQH) + (c >> 2) * 8192 + tile_off(r, c & 3);
        const char* gp = (const char*)(buf ? Ql : Qh) +
                         ((size_t)((size_t)bh * SS + q0 + r) * HD + c * 8) * 2;
        cp16(sm + off, gp);
    }

    auto load_kv = [&](int kb, int s) {
        uint32_t sb = sm + AT_STAGE + (uint32_t)s * AT_SSZ;
        #pragma unroll
        for (int t = 0; t < 8; t++) {
            int buf = t >> 1;                // 0=Kh 1=Kl 2=Vh 3=Vl
            int w = (t & 1) * 256 + tid;     // 0..511
            int r = w >> 3, c = w & 7;
            uint32_t off = (uint32_t)buf * 8192 + (c >> 2) * 4096 + tile_off(r, c & 3);
            const __nv_bfloat16* src = (buf == 0) ? Kh : (buf == 1) ? Kl : (buf == 2) ? Vh : Vl;
            const char* gp = (const char*)src + ((size_t)((size_t)bh * SS + kb + r) * HD + c * 8) * 2;
            cp16(sb + off, gp);
        }
        cp_commit();
    };

    load_kv(0, 0);
    load_kv(64, 1);

    float m0 = -1e30f, m1 = -1e30f, l0 = 0.f, l1 = 0.f;
    float acc[8][4];
    #pragma unroll
    for (int nt = 0; nt < 8; nt++)
        #pragma unroll
        for (int e = 0; e < 4; e++) acc[nt][e] = 0.f;

    const int NT = SS / 64;
    for (int it = 0; it < NT; it++) {
        if (it + 1 < NT) asm volatile("cp.async.wait_group 1;" ::: "memory");
        else             asm volatile("cp.async.wait_group 0;" ::: "memory");
        __syncthreads();
        const uint32_t sb = sm + AT_STAGE + (uint32_t)(it & 1) * AT_SSZ;

        // ---- S = Q K^T (split 3-product) ----
        float sacc[8][4];
        #pragma unroll
        for (int nt = 0; nt < 8; nt++)
            #pragma unroll
            for (int e = 0; e < 4; e++) sacc[nt][e] = 0.f;

        #pragma unroll
        for (int ks = 0; ks < 4; ks++) {
            uint32_t qoff = (uint32_t)((ks >> 1) * 8192) +
                            tile_off(warp*16 + (g & 1)*8 + l8, 2*(ks & 1) + (g >> 1));
            uint32_t qh4[4], ql4[4];
            ldsm4(qh4, sm + AT_SQH + qoff);
            ldsm4(ql4, sm + AT_SQL + qoff);
            uint32_t kh4[4][4], kl4[4][4];
            #pragma unroll
            for (int p = 0; p < 4; p++) {
                uint32_t ko = (uint32_t)((ks >> 1) * 4096) +
                              tile_off(p*16 + (g >> 1)*8 + l8, 2*(ks & 1) + (g & 1));
                ldsm4(kh4[p], sb + AT_KH + ko);
                ldsm4(kl4[p], sb + AT_KL + ko);
            }
            #pragma unroll
            for (int nt = 0; nt < 8; nt++) {
                const uint32_t* bhk = &kh4[nt >> 1][(nt & 1) * 2];
                const uint32_t* blk = &kl4[nt >> 1][(nt & 1) * 2];
                mma_bf16(sacc[nt], qh4, bhk);
                mma_bf16(sacc[nt], qh4, blk);
                mma_bf16(sacc[nt], ql4, bhk);
            }
        }

        // ---- online softmax ----
        float mx0 = -1e30f, mx1 = -1e30f;
        #pragma unroll
        for (int nt = 0; nt < 8; nt++) {
            mx0 = fmaxf(mx0, fmaxf(sacc[nt][0], sacc[nt][1]));
            mx1 = fmaxf(mx1, fmaxf(sacc[nt][2], sacc[nt][3]));
        }
        mx0 = fmaxf(mx0, __shfl_xor_sync(0xffffffffu, mx0, 1));
        mx0 = fmaxf(mx0, __shfl_xor_sync(0xffffffffu, mx0, 2));
        mx1 = fmaxf(mx1, __shfl_xor_sync(0xffffffffu, mx1, 1));
        mx1 = fmaxf(mx1, __shfl_xor_sync(0xffffffffu, mx1, 2));

        float mn0 = fmaxf(m0, mx0), mn1 = fmaxf(m1, mx1);
        float a0 = __expf(m0 - mn0), a1 = __expf(m1 - mn1);
        float rs0 = 0.f, rs1 = 0.f;
        #pragma unroll
        for (int nt = 0; nt < 8; nt++) {
            sacc[nt][0] = __expf(sacc[nt][0] - mn0);
            sacc[nt][1] = __expf(sacc[nt][1] - mn0);
            sacc[nt][2] = __expf(sacc[nt][2] - mn1);
            sacc[nt][3] = __expf(sacc[nt][3] - mn1);
            rs0 += sacc[nt][0] + sacc[nt][1];
            rs1 += sacc[nt][2] + sacc[nt][3];
        }
        rs0 += __shfl_xor_sync(0xffffffffu, rs0, 1);
        rs0 += __shfl_xor_sync(0xffffffffu, rs0, 2);
        rs1 += __shfl_xor_sync(0xffffffffu, rs1, 1);
        rs1 += __shfl_xor_sync(0xffffffffu, rs1, 2);
        l0 = l0 * a0 + rs0;  m0 = mn0;
        l1 = l1 * a1 + rs1;  m1 = mn1;
        #pragma unroll
        for (int nt = 0; nt < 8; nt++) {
            acc[nt][0] *= a0; acc[nt][1] *= a0;
            acc[nt][2] *= a1; acc[nt][3] *= a1;
        }

        // ---- O += P V (split 3-product); V row-major, trans ldmatrix ----
        #pragma unroll
        for (int ks = 0; ks < 4; ks++) {
            uint32_t aH[4], aL[4];
            #pragma unroll
            for (int half = 0; half < 2; half++) {
                int nt = 2*ks + half;
                unsigned short h0,l0s,h1,l1s,h2,l2s,h3,l3s;
                split1(sacc[nt][0], h0, l0s);
                split1(sacc[nt][1], h1, l1s);
                split1(sacc[nt][2], h2, l2s);
                split1(sacc[nt][3], h3, l3s);
                aH[half*2 + 0] = (uint32_t)h0  | ((uint32_t)h1  << 16);
                aH[half*2 + 1] = (uint32_t)h2  | ((uint32_t)h3  << 16);
                aL[half*2 + 0] = (uint32_t)l0s | ((uint32_t)l1s << 16);
                aL[half*2 + 1] = (uint32_t)l2s | ((uint32_t)l3s << 16);
            }
            uint32_t vh4[4][4], vl4[4][4];
            int vrow = 16*ks + (g & 1)*8 + l8;
            #pragma unroll
            for (int p = 0; p < 4; p++) {
                int c = p*2 + (g >> 1);            // 16B d-chunk 0..7
                uint32_t vo = (uint32_t)((c >> 2) * 4096) + tile_off(vrow, c & 3);
                ldsm4t(vh4[p], sb + AT_VH + vo);
                ldsm4t(vl4[p], sb + AT_VL + vo);
            }
            #pragma unroll
            for (int nt = 0; nt < 8; nt++) {
                const uint32_t* bhv = &vh4[nt >> 1][(nt & 1) * 2];
                const uint32_t* blv = &vl4[nt >> 1][(nt & 1) * 2];
                mma_bf16(acc[nt], aH, bhv);
                mma_bf16(acc[nt], aL, bhv);
                mma_bf16(acc[nt], aH, blv);
            }
        }

        __syncthreads();
        if (it + 2 < NT) load_kv((it + 2) * 64, it & 1);
    }

    // ---- epilogue: normalize, split to bf16 hi/lo, write [B,S,D] ----
    float i0 = 1.f / l0, i1 = 1.f / l1;
    int b = bh >> 4, h = bh & 15;
    int s0r = q0 + warp * 16 + rl;
    #pragma unroll
    for (int nt = 0; nt < 8; nt++) {
        int col = h * 64 + nt * 8 + cl;
        {
            float w0 = acc[nt][0] * i0, w1 = acc[nt][1] * i0;
            unsigned short h0,lo0,h1,lo1;
            split1(w0, h0, lo0); split1(w1, h1, lo1);
            size_t ob = (size_t)(b * SS + s0r) * DD + col;
            reinterpret_cast<uint32_t*>(Oh)[ob >> 1] = (uint32_t)h0  | ((uint32_t)h1  << 16);
            reinterpret_cast<uint32_t*>(Ol)[ob >> 1] = (uint32_t)lo0 | ((uint32_t)lo1 << 16);
        }
        {
            float w0 = acc[nt][2] * i1, w1 = acc[nt][3] * i1;
            unsigned short h0,lo0,h1,lo1;
            split1(w0, h0, lo0); split1(w1, h1, lo1);
            size_t ob = (size_t)(b * SS + s0r + 8) * DD + col;
            reinterpret_cast<uint32_t*>(Oh)[ob >> 1] = (uint32_t)h0  | ((uint32_t)h1  << 16);
            reinterpret_cast<uint32_t*>(Ol)[ob >> 1] = (uint32_t)lo0 | ((uint32_t)lo1 << 16);
        }
    }
}

// ---------------- host launch ----------------
extern "C" void kernel_launch(void* const* d_in, const int* in_sizes, int n_in,
                              void* d_out, int out_size)
{
    const float* x     = (const float*)d_in[0];
    const float* Wq    = (const float*)d_in[1];
    const float* bq    = (const float*)d_in[2];
    const float* Wk    = (const float*)d_in[3];
    const float* bk    = (const float*)d_in[4];
    const float* Wv    = (const float*)d_in[5];
    const float* bv    = (const float*)d_in[6];
    const float* Wo    = (const float*)d_in[7];
    const float* bo    = (const float*)d_in[8];
    const float* W1    = (const float*)d_in[9];
    const float* b1    = (const float*)d_in[10];
    const float* W2    = (const float*)d_in[11];
    const float* b2    = (const float*)d_in[12];
    const float* g1    = (const float*)d_in[13];
    const float* beta1 = (const float*)d_in[14];
    const float* g2    = (const float*)d_in[15];
    const float* beta2 = (const float*)d_in[16];
    float* out = (float*)d_out;

    float *x1, *bqkv;
    __nv_bfloat16 *xnh, *xnl, *xn2h, *xn2l, *ath, *atl, *hh, *hl;
    __nv_bfloat16 *qkvbh, *qkvbl;
    __nv_bfloat16 *qkvth, *qkvtl, *woth, *wotl, *w1th, *w1tl, *w2th, *w2tl;
    cudaGetSymbolAddress((void**)&x1,    g_x1);
    cudaGetSymbolAddress((void**)&bqkv,  g_bqkv);
    cudaGetSymbolAddress((void**)&xnh,   g_xn_h);
    cudaGetSymbolAddress((void**)&xnl,   g_xn_l);
    cudaGetSymbolAddress((void**)&xn2h,  g_xn2_h);
    cudaGetSymbolAddress((void**)&xn2l,  g_xn2_l);
    cudaGetSymbolAddress((void**)&ath,   g_at_h);
    cudaGetSymbolAddress((void**)&atl,   g_at_l);
    cudaGetSymbolAddress((void**)&hh,    g_h_h);
    cudaGetSymbolAddress((void**)&hl,    g_h_l);
    cudaGetSymbolAddress((void**)&qkvbh, g_qkvb_h);
    cudaGetSymbolAddress((void**)&qkvbl, g_qkvb_l);
    cudaGetSymbolAddress((void**)&qkvth, g_qkvt_h);
    cudaGetSymbolAddress((void**)&qkvtl, g_qkvt_l);
    cudaGetSymbolAddress((void**)&woth,  g_wot_h);
    cudaGetSymbolAddress((void**)&wotl,  g_wot_l);
    cudaGetSymbolAddress((void**)&w1th,  g_w1t_h);
    cudaGetSymbolAddress((void**)&w1tl,  g_w1t_l);
    cudaGetSymbolAddress((void**)&w2th,  g_w2t_h);
    cudaGetSymbolAddress((void**)&w2tl,  g_w2t_l);

    cudaFuncSetAttribute(gemm_mma, cudaFuncAttributeMaxDynamicSharedMemorySize, MSMEM);
    cudaFuncSetAttribute(attn_mma, cudaFuncAttributeMaxDynamicSharedMemorySize, ATTN_SMEM);

    // 1: all weight transposes + splits in one launch
    wsplit_all<<<dim3(32, 32, 12), 256>>>(Wq, Wk, Wv, Wo, W1, W2,
                                          qkvth, qkvtl, woth, wotl,
                                          w1th, w1tl, w2th, w2tl);
    // 2
    bias3<<<3*DD/256, 256>>>(bq, bk, bv, bqkv);
    // 3: LN1 -> split
    ln_split<<<NN, 256>>>(x, g1, beta1, xnh, xnl);

    // 4: fused QKV projection + bias + RoPE + split (q,k,v bf16 hi/lo)
    gemm_mma<<<dim3(3*DD/128, NN/128), 256, MSMEM>>>(
        xnh, xnl, qkvth, qkvtl, bqkv, nullptr, nullptr, qkvbh, qkvbl,
        NN, DD, 3*DD, MODE_QKV3);

    __nv_bfloat16* qh = qkvbh;
    __nv_bfloat16* ql = qkvbl;
    __nv_bfloat16* kh = qkvbh + (size_t)NN*DD;
    __nv_bfloat16* kl = qkvbl + (size_t)NN*DD;
    __nv_bfloat16* vh = qkvbh + 2*(size_t)NN*DD;
    __nv_bfloat16* vl = qkvbl + 2*(size_t)NN*DD;

    // 5: MMA flash attention -> bf16 hi/lo attn output [B,S,D]
    attn_mma<<<dim3(SS/128, BB*HH), 256, ATTN_SMEM>>>(qh, ql, kh, kl, vh, vl, ath, atl);

    // 6: x1 = x + attn @ Wo + bo
    gemm_mma<<<dim3(DD/128, NN/128), 256, MSMEM>>>(
        ath, atl, woth, wotl, bo, x, x1, nullptr, nullptr,
        NN, DD, DD, MODE_RESID);

    // 7: LN2 -> split
    ln_split<<<NN, 256>>>(x1, g2, beta2, xn2h, xn2l);

    // 8: FFN up: relu + split epilogue
    gemm_mma<<<dim3(FF/128, NN/128), 256, MSMEM>>>(
        xn2h, xn2l, w1th, w1tl, b1, nullptr, nullptr, hh, hl,
        NN, DD, FF, MODE_RELU_SPLIT);

    // 9: FFN down + residual -> out
    gemm_mma<<<dim3(DD/128, NN/128), 256, MSMEM>>>(
        hh, hl, w2th, w2tl, b2, x1, out, nullptr, nullptr,
        NN, FF, DD, MODE_RESID);
}